// round 1
// baseline (speedup 1.0000x reference)
#include <cuda_runtime.h>
#include <cstdint>
#include <math.h>

// ----------------------------------------------------------------------------
// WaveNet on GB300 — round 1: correct fp32 SIMT baseline, GEMM-ified.
//
// Shapes (fixed by the problem):
//   B=4, T=18308, NQ=256, NR=384, ND=256, NS=256, NP=512, NCOND=256
//   20 layers, FS=2, dils = [1..512]x2, TOTAL_LW=2046, OUT_T=16262
//
// Restructure: keep x in absolute-time buffers X[b][384][T]; layer i updates
// t in [cl_i, T):  z[t] = act(Wcat · [X(t-dil); X(t); cond(t)]),
//                  Xnew[t] = Wres·z[t] + Xold[t],  skip[t-2046] += Wskip·z[t]
// ----------------------------------------------------------------------------

#define TFULL 18308
#define OUTT  16262   // 18308 - 2046

// ---------------- scratch (device globals: allocation-free) -----------------
__device__ float g_X0[4u*384u*18308u];
__device__ float g_X1[4u*384u*18308u];
__device__ float g_cond[4u*256u*18308u];
__device__ float g_Z[4u*256u*18308u];
__device__ float g_skip[4u*256u*16262u];
__device__ float g_H[4u*512u*16262u];
__device__ float g_Wcat[20u*512u*1024u];   // interleaved [2d]=filt,[2d+1]=gate ; K = 384|384|256
__device__ float g_WB[20u*640u*256u];      // rows 0..255 skip, 256..639 res
__device__ float g_fb[20u*512u];
__device__ float g_lc1[4u*128u*62u];
__device__ float g_upA[4u*128u*4580u];
__device__ float g_upB[4u*128u*4580u];

// ---------------- weight packing --------------------------------------------
__global__ void pack_weights(const float* __restrict__ sig_w, const float* __restrict__ sig_b,
                             const float* __restrict__ gate_w, const float* __restrict__ gate_b,
                             const float* __restrict__ psig_w, const float* __restrict__ pgate_w,
                             const float* __restrict__ skp_w, const float* __restrict__ res_w)
{
    int idx = blockIdx.x * blockDim.x + threadIdx.x;
    const int NW = 20*512*1024;
    if (idx < NW) {
        int l = idx / (512*1024); int r = idx % (512*1024);
        int m = r / 1024;         int k = r % 1024;
        int d = m >> 1;           int gte = m & 1;
        const float* ws = gte ? gate_w : sig_w;
        const float* wp = gte ? pgate_w : psig_w;
        float v;
        if (k < 384)       v = ws[((size_t)(l*256 + d)*384 + k)*2 + 0];
        else if (k < 768)  v = ws[((size_t)(l*256 + d)*384 + (k-384))*2 + 1];
        else               v = wp[(size_t)(l*256 + d)*256 + (k-768)];
        g_Wcat[idx] = v;
    }
    const int NB = 20*640*256;
    if (idx < NB) {
        int l = idx / (640*256); int r = idx % (640*256);
        int m = r / 256;         int k = r % 256;
        g_WB[idx] = (m < 256) ? skp_w[(size_t)(l*256 + m)*256 + k]
                              : res_w[(size_t)(l*384 + (m-256))*256 + k];
    }
    if (idx < 20*512) {
        int l = idx / 512; int m = idx % 512; int d = m >> 1;
        g_fb[idx] = (m & 1) ? gate_b[l*256 + d] : sig_b[l*256 + d];
    }
}

// ---------------- conditioning path ------------------------------------------
// lc gather + conv(k=3): out (4,128,62)
__global__ void lc1_kernel(const float* __restrict__ lc_sparse, const int* __restrict__ jit,
                           const float* __restrict__ w, const float* __restrict__ bias)
{
    int o = blockIdx.x, b = blockIdx.y;
    int tx = threadIdx.x;               // 64 threads
    __shared__ int   js[64];
    __shared__ float lcs[64][65];
    js[tx] = jit[b*64 + tx];
    __syncthreads();
    for (int s = 0; s < 64; s++)
        lcs[tx][s] = lc_sparse[(size_t)(b*64 + tx)*64 + js[s]];
    __syncthreads();
    if (tx < 62) {
        float acc = bias[o];
        for (int c = 0; c < 64; c++) {
            const float* wr = &w[(size_t)(o*64 + c)*3];
            acc += wr[0]*lcs[c][tx] + wr[1]*lcs[c][tx+1] + wr[2]*lcs[c][tx+2];
        }
        g_lc1[(size_t)(b*128 + o)*62 + tx] = acc;
    }
}

// transposed conv (gather form). w layout: [a(in)][o(out)][K], tap at K-1-k.
__global__ void tconv_kernel(const float* __restrict__ in, const float* __restrict__ w,
                             const float* __restrict__ bias, float* __restrict__ out,
                             int Lin, int Lout, int Kk, int S,
                             int inCh, int inB, int outCh, int outB)
{
    int t = blockIdx.x * blockDim.x + threadIdx.x;
    int o = blockIdx.y, b = blockIdx.z;
    if (t >= Lout) return;
    int r = (S - 1 - t) % S; if (r < 0) r += S;
    int u0 = (t + r - S + 1) / S;
    int jmax = (Kk - r + S - 1) / S;
    int jlim = Lin - u0; if (jlim < jmax) jmax = jlim;
    float acc = bias[o];
    for (int a = 0; a < 128; a++) {
        const float* inr = in + (size_t)b*inB + (size_t)a*inCh + u0;
        const float* wr  = w + (size_t)(a*128 + o)*Kk + (Kk - 1 - r);
        for (int j = 0; j < jmax; j++)
            acc += inr[j] * wr[-j*S];
    }
    out[(size_t)b*outB + (size_t)o*outCh + t] = acc;
}

// global-conditioning broadcast into cond channels 128..255
__global__ void gc_kernel(const float* __restrict__ emb_w, const float* __restrict__ emb_b,
                          const int* __restrict__ spk)
{
    int t = blockIdx.x * blockDim.x + threadIdx.x;
    int c = blockIdx.y, b = blockIdx.z;
    if (t < TFULL) {
        float v = emb_w[c*40 + spk[b]] + emb_b[c];
        g_cond[((size_t)(b*256) + 128 + c)*TFULL + t] = v;
    }
}

// ---------------- fused 128x128x8 fp32 GEMM -----------------------------------
// MODE 0: base   (M=384,K=256)  out = W·wav + b             -> X0
// MODE 1: layerA (M=512,K=1024) z = tanh(f)·sigmoid(g)      -> Z
// MODE 2: layerB (M=640,K=256)  skip accum + residual add   -> skip, Xout
// MODE 3: post1  (M=512,K=256)  relu(W·relu(skip)+b)        -> H
template<int MODE>
__global__ __launch_bounds__(256, 2) void gemm_fused(
    const float* __restrict__ W, const float* __restrict__ S0, const float* __restrict__ S1,
    const float* __restrict__ bias, float* __restrict__ O0,
    const float* __restrict__ Xold, float* __restrict__ skipbuf,
    int tStart, int tLen, int dil, int first)
{
    constexpr int K  = (MODE == 1) ? 1024 : 256;
    constexpr int BM = 128, BN = 128, BK = 8;
    constexpr int nK = K / BK;
    __shared__ float As[2][BK][BM];
    __shared__ float Bs[2][BK][BN];

    const int tid = threadIdx.x;
    const int tx = tid & 15, ty = tid >> 4;
    const int bx = blockIdx.x, m0 = blockIdx.y * BM, bb = blockIdx.z;
    const int ar = tid >> 1, ac = (tid & 1) * 4;
    const int br = tid >> 5, bc = (tid & 31) * 4;
    const int tBase = tStart + bx * BN;
    const bool fullTile = (bx * BN + BN) <= tLen;

    auto fetchA = [&](int kt) -> float4 {
        return *reinterpret_cast<const float4*>(&W[(size_t)(m0 + ar) * K + kt * BK + ac]);
    };
    auto fetchB = [&](int kt, float v[4]) {
        int k = kt * BK + br;
        const float* p;
        if (MODE == 1) {
            if (k < 384)      p = S0 + ((size_t)(bb*384 + k))*TFULL + (tBase - dil) + bc;
            else if (k < 768) p = S0 + ((size_t)(bb*384 + (k-384)))*TFULL + tBase + bc;
            else              p = S1 + ((size_t)(bb*256 + (k-768)))*TFULL + tBase + bc;
        } else if (MODE == 3) {
            p = S0 + ((size_t)(bb*256 + k))*OUTT + tBase + bc;
        } else {
            p = S0 + ((size_t)(bb*256 + k))*TFULL + tBase + bc;
        }
        if (fullTile) {
            v[0] = p[0]; v[1] = p[1]; v[2] = p[2]; v[3] = p[3];
        } else {
            int base = bx * BN + bc;
            #pragma unroll
            for (int e = 0; e < 4; e++) v[e] = (base + e < tLen) ? p[e] : 0.f;
        }
        if (MODE == 3) {
            #pragma unroll
            for (int e = 0; e < 4; e++) v[e] = fmaxf(v[e], 0.f);
        }
    };

    float acc[8][8];
    #pragma unroll
    for (int i = 0; i < 8; i++)
        #pragma unroll
        for (int j = 0; j < 8; j++) acc[i][j] = 0.f;

    {   // stage 0
        float4 av = fetchA(0); float bv[4]; fetchB(0, bv);
        As[0][ac+0][ar] = av.x; As[0][ac+1][ar] = av.y; As[0][ac+2][ar] = av.z; As[0][ac+3][ar] = av.w;
        Bs[0][br][bc+0] = bv[0]; Bs[0][br][bc+1] = bv[1]; Bs[0][br][bc+2] = bv[2]; Bs[0][br][bc+3] = bv[3];
    }
    __syncthreads();

    int buf = 0;
    for (int kt = 0; kt < nK; kt++) {
        float4 av; float bv[4];
        if (kt + 1 < nK) { av = fetchA(kt + 1); fetchB(kt + 1, bv); }
        #pragma unroll
        for (int kk = 0; kk < BK; kk++) {
            float a[8], bl[8];
            *reinterpret_cast<float4*>(&a[0])  = *reinterpret_cast<const float4*>(&As[buf][kk][ty*8]);
            *reinterpret_cast<float4*>(&a[4])  = *reinterpret_cast<const float4*>(&As[buf][kk][ty*8+4]);
            *reinterpret_cast<float4*>(&bl[0]) = *reinterpret_cast<const float4*>(&Bs[buf][kk][tx*8]);
            *reinterpret_cast<float4*>(&bl[4]) = *reinterpret_cast<const float4*>(&Bs[buf][kk][tx*8+4]);
            #pragma unroll
            for (int i = 0; i < 8; i++)
                #pragma unroll
                for (int j = 0; j < 8; j++)
                    acc[i][j] += a[i] * bl[j];
        }
        if (kt + 1 < nK) {
            int nb = buf ^ 1;
            As[nb][ac+0][ar] = av.x; As[nb][ac+1][ar] = av.y; As[nb][ac+2][ar] = av.z; As[nb][ac+3][ar] = av.w;
            Bs[nb][br][bc+0] = bv[0]; Bs[nb][br][bc+1] = bv[1]; Bs[nb][br][bc+2] = bv[2]; Bs[nb][br][bc+3] = bv[3];
            __syncthreads();
            buf = nb;
        }
    }

    // ---------------- epilogues ----------------
    const int colBase = bx * BN + tx * 8;
    if (MODE == 0) {
        #pragma unroll
        for (int i = 0; i < 8; i++) {
            int m = m0 + ty*8 + i;
            float bv = bias[m];
            float* orow = O0 + ((size_t)(bb*384 + m))*TFULL + tBase + tx*8;
            #pragma unroll
            for (int j = 0; j < 8; j++)
                if (colBase + j < tLen) orow[j] = acc[i][j] + bv;
        }
    } else if (MODE == 1) {
        #pragma unroll
        for (int p = 0; p < 4; p++) {
            int m = m0 + ty*8 + 2*p;
            int d = m >> 1;
            float bf = bias[m], bg = bias[m+1];
            float* zrow = O0 + ((size_t)(bb*256 + d))*TFULL + tBase + tx*8;
            #pragma unroll
            for (int j = 0; j < 8; j++) {
                if (colBase + j < tLen) {
                    float f = acc[2*p][j]   + bf;
                    float g = acc[2*p+1][j] + bg;
                    zrow[j] = tanhf(f) * (1.f / (1.f + expf(-g)));
                }
            }
        }
    } else if (MODE == 2) {
        #pragma unroll
        for (int i = 0; i < 8; i++) {
            int m = m0 + ty*8 + i;
            if (m < 256) {
                float* srow = skipbuf + ((size_t)(bb*256 + m))*OUTT;
                #pragma unroll
                for (int j = 0; j < 8; j++) {
                    if (colBase + j < tLen) {
                        int ts = tBase + tx*8 + j - 2046;
                        if (ts >= 0) {
                            if (first) srow[ts] = acc[i][j];
                            else       srow[ts] += acc[i][j];
                        }
                    }
                }
            } else {
                size_t off = ((size_t)(bb*384 + (m-256)))*TFULL + tBase + tx*8;
                #pragma unroll
                for (int j = 0; j < 8; j++)
                    if (colBase + j < tLen) O0[off+j] = acc[i][j] + Xold[off+j];
            }
        }
    } else { // MODE 3
        #pragma unroll
        for (int i = 0; i < 8; i++) {
            int m = m0 + ty*8 + i;
            float bv = bias[m];
            float* orow = O0 + ((size_t)(bb*512 + m))*OUTT + tBase + tx*8;
            #pragma unroll
            for (int j = 0; j < 8; j++)
                if (colBase + j < tLen) orow[j] = fmaxf(acc[i][j] + bv, 0.f);
        }
    }
}

// ---------------- post2 + log_softmax ----------------------------------------
__global__ __launch_bounds__(256) void post2_softmax(const float* __restrict__ H,
                                                     const float* __restrict__ W2,
                                                     const float* __restrict__ B2,
                                                     float* __restrict__ out)
{
    int b = blockIdx.y;
    int t0 = blockIdx.x * 16;
    int q = threadIdx.x;                 // 0..255
    __shared__ float Hs[512*16];         // 32KB; reused as Vs after GEMM
    __shared__ float Ws[256*16];         // 16KB; reused for lse

    for (int idx = q; idx < 512*16; idx += 256) {
        int p = idx >> 4, j = idx & 15;
        int t = t0 + j;
        Hs[idx] = (t < OUTT) ? H[((size_t)(b*512 + p))*OUTT + t] : 0.f;
    }
    float acc[16];
    float bq = B2[q];
    #pragma unroll
    for (int j = 0; j < 16; j++) acc[j] = bq;

    for (int p0 = 0; p0 < 512; p0 += 16) {
        __syncthreads();
        for (int idx = q; idx < 256*16; idx += 256) {
            int qq = idx >> 4, pp = idx & 15;
            Ws[idx] = W2[(size_t)qq*512 + p0 + pp];
        }
        __syncthreads();
        #pragma unroll
        for (int pp = 0; pp < 16; pp++) {
            float w = Ws[q*16 + pp];
            const float* hp = &Hs[(p0 + pp)*16];
            #pragma unroll
            for (int j = 0; j < 16; j++) acc[j] += w * hp[j];
        }
    }
    __syncthreads();
    #pragma unroll
    for (int j = 0; j < 16; j++) Hs[q*16 + j] = acc[j];   // Vs
    __syncthreads();
    if (q < 16) {
        float mx = -1e30f;
        for (int qq = 0; qq < 256; qq++) mx = fmaxf(mx, Hs[qq*16 + q]);
        float s = 0.f;
        for (int qq = 0; qq < 256; qq++) s += expf(Hs[qq*16 + q] - mx);
        Ws[q] = mx + logf(s);
    }
    __syncthreads();
    #pragma unroll
    for (int j = 0; j < 16; j++) {
        int t = t0 + j;
        if (t < OUTT) out[((size_t)(b*256 + q))*OUTT + t] = acc[j] - Ws[j];
    }
}

// ---------------- host --------------------------------------------------------
static const int h_dils[20] = {1,2,4,8,16,32,64,128,256,512,1,2,4,8,16,32,64,128,256,512};

extern "C" void kernel_launch(void* const* d_in, const int* in_sizes, int n_in,
                              void* d_out, int out_size)
{
    (void)in_sizes; (void)n_in; (void)out_size;
    const float* wav       = (const float*)d_in[0];
    const float* lc_sparse = (const float*)d_in[1];
    const float* lc_conv_w = (const float*)d_in[2];
    const float* lc_conv_b = (const float*)d_in[3];
    const float* ups_w0    = (const float*)d_in[4];
    const float* ups_b0    = (const float*)d_in[5];
    const float* ups_w1    = (const float*)d_in[6];
    const float* ups_b1    = (const float*)d_in[7];
    const float* ups_w2    = (const float*)d_in[8];
    const float* ups_b2    = (const float*)d_in[9];
    const float* ups_w3    = (const float*)d_in[10];
    const float* ups_b3    = (const float*)d_in[11];
    const float* emb_w     = (const float*)d_in[12];
    const float* emb_b     = (const float*)d_in[13];
    const float* base_w    = (const float*)d_in[14];
    const float* base_b    = (const float*)d_in[15];
    const float* sig_w     = (const float*)d_in[16];
    const float* sig_b     = (const float*)d_in[17];
    const float* gate_w    = (const float*)d_in[18];
    const float* gate_b    = (const float*)d_in[19];
    const float* psig_w    = (const float*)d_in[20];
    const float* pgate_w   = (const float*)d_in[21];
    const float* skp_w     = (const float*)d_in[22];
    const float* res_w     = (const float*)d_in[23];
    const float* post1_w   = (const float*)d_in[24];
    const float* post1_b   = (const float*)d_in[25];
    const float* post2_w   = (const float*)d_in[26];
    const float* post2_b   = (const float*)d_in[27];
    const int*   spk       = (const int*)d_in[28];
    const int*   jit       = (const int*)d_in[29];
    float* out = (float*)d_out;

    float *pX0, *pX1, *pCond, *pZ, *pSkip, *pH, *pWcat, *pWB, *pfb, *pLc1, *pUpA, *pUpB;
    cudaGetSymbolAddress((void**)&pX0,   g_X0);
    cudaGetSymbolAddress((void**)&pX1,   g_X1);
    cudaGetSymbolAddress((void**)&pCond, g_cond);
    cudaGetSymbolAddress((void**)&pZ,    g_Z);
    cudaGetSymbolAddress((void**)&pSkip, g_skip);
    cudaGetSymbolAddress((void**)&pH,    g_H);
    cudaGetSymbolAddress((void**)&pWcat, g_Wcat);
    cudaGetSymbolAddress((void**)&pWB,   g_WB);
    cudaGetSymbolAddress((void**)&pfb,   g_fb);
    cudaGetSymbolAddress((void**)&pLc1,  g_lc1);
    cudaGetSymbolAddress((void**)&pUpA,  g_upA);
    cudaGetSymbolAddress((void**)&pUpB,  g_upB);

    // weight packing
    {
        int n = 20*512*1024;
        pack_weights<<<(n + 255)/256, 256>>>(sig_w, sig_b, gate_w, gate_b,
                                             psig_w, pgate_w, skp_w, res_w);
    }

    // conditioning path
    lc1_kernel<<<dim3(128, 4), 64>>>(lc_sparse, jit, lc_conv_w, lc_conv_b);
    tconv_kernel<<<dim3((290+127)/128, 128, 4), 128>>>(pLc1, ups_w0, ups_b0, pUpA,
        62, 290, 25, 5, 62, 128*62, 290, 128*290);
    tconv_kernel<<<dim3((1148+127)/128, 128, 4), 128>>>(pUpA, ups_w1, ups_b1, pUpB,
        290, 1148, 16, 4, 290, 128*290, 1148, 128*1148);
    tconv_kernel<<<dim3((4580+127)/128, 128, 4), 128>>>(pUpB, ups_w2, ups_b2, pUpA,
        1148, 4580, 16, 4, 1148, 128*1148, 4580, 128*4580);
    tconv_kernel<<<dim3((TFULL+127)/128, 128, 4), 128>>>(pUpA, ups_w3, ups_b3, pCond,
        4580, TFULL, 16, 4, 4580, 128*4580, TFULL, 256*TFULL);
    gc_kernel<<<dim3((TFULL+255)/256, 128, 4), 256>>>(emb_w, emb_b, spk);

    // base 1x1 conv -> X0
    gemm_fused<0><<<dim3((TFULL+127)/128, 3, 4), 256>>>(base_w, wav, nullptr, base_b,
        pX0, nullptr, nullptr, 0, TFULL, 0, 0);

    // 20 residual layers
    int cum = 0;
    for (int i = 0; i < 20; i++) {
        int dil = h_dils[i];
        int cl = cum + dil;
        int tLen = TFULL - cl;
        float* Xin  = (i % 2 == 0) ? pX0 : pX1;
        float* Xout = (i % 2 == 0) ? pX1 : pX0;
        int gx = (tLen + 127)/128;
        gemm_fused<1><<<dim3(gx, 4, 4), 256>>>(pWcat + (size_t)i*512*1024, Xin, pCond,
            pfb + i*512, pZ, nullptr, nullptr, cl, tLen, dil, 0);
        gemm_fused<2><<<dim3(gx, 5, 4), 256>>>(pWB + (size_t)i*640*256, pZ, nullptr,
            nullptr, Xout, Xin, pSkip, cl, tLen, 0, (i == 0) ? 1 : 0);
        cum = cl;
    }

    // post layers
    gemm_fused<3><<<dim3((OUTT+127)/128, 4, 4), 256>>>(post1_w, pSkip, nullptr, post1_b,
        pH, nullptr, nullptr, 0, OUTT, 0, 0);
    post2_softmax<<<dim3((OUTT+15)/16, 4), 256>>>(pH, post2_w, post2_b, out);
}

// round 8
// speedup vs baseline: 1.1191x; 1.1191x over previous
#include <cuda_runtime.h>
#include <cstdint>
#include <math.h>

// ----------------------------------------------------------------------------
// WaveNet on GB300/B200 — round 7: 3xTF32 mma.sync GEMMs.
// FIX vs R6/R7: epilogue column guards now use GLOBAL column (cbase+col),
// eliminating last-tile row-overrun corruption of X/skip/H.
//   B=4, T=18308, 20 layers, dils [1..512]x2, TOTAL_LW=2046, OUTT=16262
// ----------------------------------------------------------------------------

#define TFULL 18308
#define OUTT  16262
#define OUTTP 16264      // padded row stride (mult of 8) for skip/H
#define SLACK 4096
#define LEAD  64

#define XSZ   (4u*384u*18308u)
#define CSZ   (4u*256u*18308u)
#define SSZ   (4u*256u*16264u)

// ---------------- scratch (device globals: allocation-free, zero-init) ------
__device__ __align__(128) float g_Xh0[XSZ + SLACK + LEAD];
__device__ __align__(128) float g_Xl0[XSZ + SLACK + LEAD];
__device__ __align__(128) float g_Xh1[XSZ + SLACK + LEAD];
__device__ __align__(128) float g_Xl1[XSZ + SLACK + LEAD];
__device__ __align__(128) float g_condh[CSZ + SLACK];
__device__ __align__(128) float g_condl[CSZ + SLACK];
__device__ __align__(128) float g_condF[4u*128u*18308u];
__device__ __align__(128) float g_Zh[CSZ + SLACK];
__device__ __align__(128) float g_Zl[CSZ + SLACK];
__device__ __align__(128) float g_wavh[CSZ + SLACK];
__device__ __align__(128) float g_wavl[CSZ + SLACK];
__device__ __align__(128) float g_skip[SSZ + SLACK];
__device__ __align__(128) float g_skh[SSZ + SLACK];
__device__ __align__(128) float g_skl[SSZ + SLACK];
__device__ __align__(128) float g_H[4u*512u*16264u + SLACK];
__device__ __align__(128) float g_Wcat[20u*512u*3072u];  // [Wh|Wl|Wh], 16-row filt/gate interleave
__device__ __align__(128) float g_WB[20u*640u*768u];     // [Wh|Wl|Wh]; rows 0..255 skip, 256..639 res
__device__ __align__(128) float g_WbA[384u*768u];        // base_w augmented
__device__ __align__(128) float g_Wp1[512u*768u];        // post1_w augmented
__device__ __align__(128) float g_fb[20u*512u];
__device__ __align__(128) float g_lc1[4u*128u*62u];
__device__ __align__(128) float g_upA[4u*128u*4580u];
__device__ __align__(128) float g_upB[4u*128u*4580u];

// ---------------- helpers -----------------------------------------------------
__device__ __forceinline__ uint32_t sptr(const void* p) {
    return (uint32_t)__cvta_generic_to_shared(p);
}
#define CP16(dst, src) \
    asm volatile("cp.async.cg.shared.global [%0], [%1], 16;\n" :: "r"(dst), "l"(src))
#define CP4(dst, src) \
    asm volatile("cp.async.ca.shared.global [%0], [%1], 4;\n" :: "r"(dst), "l"(src))
#define CP_COMMIT() asm volatile("cp.async.commit_group;\n")

__device__ __forceinline__ void mma_tf32(float c[4], const uint32_t a[4], const uint32_t b[2]) {
    asm volatile(
        "mma.sync.aligned.m16n8k8.row.col.f32.tf32.tf32.f32 "
        "{%0,%1,%2,%3}, {%4,%5,%6,%7}, {%8,%9}, {%0,%1,%2,%3};"
        : "+f"(c[0]), "+f"(c[1]), "+f"(c[2]), "+f"(c[3])
        : "r"(a[0]), "r"(a[1]), "r"(a[2]), "r"(a[3]), "r"(b[0]), "r"(b[1]));
}
__device__ __forceinline__ float rna(float v) {
    uint32_t r; asm("cvt.rna.tf32.f32 %0, %1;" : "=r"(r) : "f"(v));
    return __uint_as_float(r);
}
__device__ __forceinline__ float fast_sig(float x) {
    float e; asm("ex2.approx.f32 %0, %1;" : "=f"(e) : "f"(-x * 1.4426950408889634f));
    float r; asm("rcp.approx.f32 %0, %1;" : "=f"(r) : "f"(1.f + e));
    return r;
}
__device__ __forceinline__ float acc_tanh(float x) {     // 2*sig(2x)-1, abs err ~2e-6
    return 2.f * fast_sig(2.f * x) - 1.f;
}

// ---------------- weight packing (hi|lo|hi augmented) ------------------------
__global__ void pack_weights(const float* __restrict__ sig_w, const float* __restrict__ sig_b,
                             const float* __restrict__ gate_w, const float* __restrict__ gate_b,
                             const float* __restrict__ psig_w, const float* __restrict__ pgate_w,
                             const float* __restrict__ skp_w, const float* __restrict__ res_w,
                             const float* __restrict__ base_w, const float* __restrict__ post1_w)
{
    int idx = blockIdx.x * blockDim.x + threadIdx.x;
    if (idx < 20*512*3072) {
        int l = idx / (512*3072); int r = idx % (512*3072);
        int m = r / 3072;         int kp = r % 3072;
        int sel = kp >> 10;       int k = kp & 1023;       // 0:hi 1:lo 2:hi
        int blk = m >> 4;         int rr = m & 15;
        int d = blk*8 + (rr & 7); int gte = rr >> 3;
        const float* ws = gte ? gate_w : sig_w;
        const float* wp = gte ? pgate_w : psig_w;
        float v;
        if (k < 384)       v = ws[((size_t)(l*256 + d)*384 + k)*2 + 0];
        else if (k < 768)  v = ws[((size_t)(l*256 + d)*384 + (k-384))*2 + 1];
        else               v = wp[(size_t)(l*256 + d)*256 + (k-768)];
        float h = rna(v);
        g_Wcat[idx] = (sel == 1) ? rna(v - h) : h;
    }
    if (idx < 20*640*768) {
        int l = idx / (640*768); int r = idx % (640*768);
        int m = r / 768;         int kp = r % 768;
        int sel = kp >> 8;       int k = kp & 255;
        float v = (m < 256) ? skp_w[(size_t)(l*256 + m)*256 + k]
                            : res_w[(size_t)(l*384 + (m-256))*256 + k];
        float h = rna(v);
        g_WB[idx] = (sel == 1) ? rna(v - h) : h;
    }
    if (idx < 384*768) {
        int m = idx / 768; int kp = idx % 768;
        int sel = kp >> 8; int k = kp & 255;
        float v = base_w[m*256 + k];
        float h = rna(v);
        g_WbA[idx] = (sel == 1) ? rna(v - h) : h;
    }
    if (idx < 512*768) {
        int m = idx / 768; int kp = idx % 768;
        int sel = kp >> 8; int k = kp & 255;
        float v = post1_w[m*256 + k];
        float h = rna(v);
        g_Wp1[idx] = (sel == 1) ? rna(v - h) : h;
    }
    if (idx < 20*512) {
        int l = idx / 512; int m = idx % 512;
        int blk = m >> 4;  int rr = m & 15;
        int d = blk*8 + (rr & 7); int gte = rr >> 3;
        g_fb[idx] = gte ? gate_b[l*256 + d] : sig_b[l*256 + d];
    }
}

// ---------------- split kernels ----------------------------------------------
__global__ void split_flat(const float* __restrict__ src, float* __restrict__ h,
                           float* __restrict__ l, int n, int do_relu)
{
    int i = blockIdx.x * blockDim.x + threadIdx.x;
    if (i < n) {
        float v = src[i];
        if (do_relu) v = fmaxf(v, 0.f);
        float hh = rna(v);
        h[i] = hh; l[i] = rna(v - hh);
    }
}
__global__ void split_cond(const float* __restrict__ src, float* __restrict__ h,
                           float* __restrict__ l)
{
    int i = blockIdx.x * blockDim.x + threadIdx.x;
    const int n = 4*128*TFULL;
    if (i < n) {
        int t = i % TFULL; int rc = i / TFULL;
        int c = rc & 127;  int b = rc >> 7;
        float v = src[i];
        float hh = rna(v);
        size_t o = ((size_t)(b*256) + c)*TFULL + t;
        h[o] = hh; l[o] = rna(v - hh);
    }
}

// ---------------- conditioning path ------------------------------------------
__global__ void lc1_kernel(const float* __restrict__ lc_sparse, const int* __restrict__ jit,
                           const float* __restrict__ w, const float* __restrict__ bias)
{
    int o = blockIdx.x, b = blockIdx.y;
    int tx = threadIdx.x;               // 64 threads
    __shared__ int   js[64];
    __shared__ float lcs[64][65];
    js[tx] = jit[b*64 + tx];
    __syncthreads();
    for (int s = 0; s < 64; s++)
        lcs[tx][s] = lc_sparse[(size_t)(b*64 + tx)*64 + js[s]];
    __syncthreads();
    if (tx < 62) {
        float acc = bias[o];
        for (int c = 0; c < 64; c++) {
            const float* wr = &w[(size_t)(o*64 + c)*3];
            acc += wr[0]*lcs[c][tx] + wr[1]*lcs[c][tx+1] + wr[2]*lcs[c][tx+2];
        }
        g_lc1[(size_t)(b*128 + o)*62 + tx] = acc;
    }
}

__global__ void tconv_kernel(const float* __restrict__ in, const float* __restrict__ w,
                             const float* __restrict__ bias, float* __restrict__ out,
                             int Lin, int Lout, int Kk, int S,
                             int inCh, int inB, int outCh, int outB)
{
    int t = blockIdx.x * blockDim.x + threadIdx.x;
    int o = blockIdx.y, b = blockIdx.z;
    if (t >= Lout) return;
    int r = (S - 1 - t) % S; if (r < 0) r += S;
    int u0 = (t + r - S + 1) / S;
    int jmax = (Kk - r + S - 1) / S;
    int jlim = Lin - u0; if (jlim < jmax) jmax = jlim;
    float acc = bias[o];
    for (int a = 0; a < 128; a++) {
        const float* inr = in + (size_t)b*inB + (size_t)a*inCh + u0;
        const float* wr  = w + (size_t)(a*128 + o)*Kk + (Kk - 1 - r);
        for (int j = 0; j < jmax; j++)
            acc += inr[j] * wr[-j*S];
    }
    out[(size_t)b*outB + (size_t)o*outCh + t] = acc;
}

__global__ void gc_kernel(const float* __restrict__ emb_w, const float* __restrict__ emb_b,
                          const int* __restrict__ spk,
                          float* __restrict__ ch, float* __restrict__ clo)
{
    int t = blockIdx.x * blockDim.x + threadIdx.x;
    int c = blockIdx.y, b = blockIdx.z;
    if (t < TFULL) {
        float v = emb_w[c*40 + spk[b]] + emb_b[c];
        float h = rna(v), l = rna(v - h);
        size_t o = ((size_t)(b*256) + 128 + c)*TFULL + t;
        ch[o] = h; clo[o] = l;
    }
}

// ---------------- 3xTF32 tensor-core fused GEMM (augmented K) -----------------
// 128x128 tile, BK=16, 256 threads (8 warps, 2x4), warp tile 64x32, m16n8k8.
// K' = 3*K; B' chunks: [0,K)=hi, [K,2K)=hi, [2K,3K)=lo.
template<int MODE>
__global__ __launch_bounds__(256, 2) void gemm_tc(
    const float* __restrict__ W,
    const float* __restrict__ S0h, const float* __restrict__ S0l,
    const float* __restrict__ S1h, const float* __restrict__ S1l,
    const float* __restrict__ bias,
    float* __restrict__ O0, float* __restrict__ O1,
    const float* __restrict__ X2h, const float* __restrict__ X2l,
    float* __restrict__ skipbuf,
    int tStart, int tLen, int dil, int first, int tMin)
{
    constexpr int KB = (MODE == 1) ? 1024 : 256;   // base (un-augmented) K
    constexpr int K  = 3 * KB;                     // augmented
    constexpr int BM = 128, BN = 128, BK = 16;
    constexpr int nK = K / BK;
    constexpr int SIN = (MODE == 3) ? OUTTP : TFULL;
    __shared__ __align__(16) float As[2][BM][20];
    __shared__ __align__(16) float Bs[2][BK][136];

    const int tid  = threadIdx.x;
    const int lane = tid & 31, warp = tid >> 5;
    const int g    = lane >> 2, tig = lane & 3;
    const int wm0  = (warp >> 2) * 64, wn0 = (warp & 3) * 32;
    const int bx = blockIdx.x, m0 = blockIdx.y * BM, bb = blockIdx.z;
    const int tBase = tStart + bx * BN;
    const int cbase = bx * BN;                     // GLOBAL column base (the R6/R7 bugfix)

    const int ar = tid >> 1, ac = (tid & 1) * 8;     // A: row ar, cols ac..ac+7
    const int br = tid >> 5, bc = (tid & 31) * 4;    // B: rows br,br+8, cols bc..bc+3

    auto rowptr = [&](int k) -> const float* {
        bool lo = (k >= 2*KB);
        int kk = (k >= 2*KB) ? (k - 2*KB) : ((k >= KB) ? (k - KB) : k);
        if (MODE == 1) {
            const float* Xs = lo ? S0l : S0h;
            const float* Cs = lo ? S1l : S1h;
            if (kk < 384)      return Xs + ((size_t)(bb*384 + kk))*TFULL + (tBase - dil);
            else if (kk < 768) return Xs + ((size_t)(bb*384 + (kk-384)))*TFULL + tBase;
            else               return Cs + ((size_t)(bb*256 + (kk-768)))*TFULL + tBase;
        } else {
            const float* Ss = lo ? S0l : S0h;
            return Ss + ((size_t)(bb*256 + kk))*SIN + tBase;
        }
    };
    auto cpB = [&](uint32_t dst, const float* p) {
        if ((((uintptr_t)p) & 15) == 0) {
            CP16(dst, p);
        } else {
            #pragma unroll
            for (int e = 0; e < 4; e++) CP4(dst + 4*e, p + e);
        }
    };
    auto issueStage = [&](int kt, int s) {
        const float* asrc = W + (size_t)(m0 + ar) * K + kt * BK + ac;
        uint32_t ad = sptr(&As[s][ar][ac]);
        CP16(ad,      asrc);
        CP16(ad + 16, asrc + 4);
        cpB(sptr(&Bs[s][br][bc]),     rowptr(kt*BK + br)     + bc);
        cpB(sptr(&Bs[s][br + 8][bc]), rowptr(kt*BK + br + 8) + bc);
    };

    float acc[4][4][4];
    #pragma unroll
    for (int mi = 0; mi < 4; mi++)
        #pragma unroll
        for (int ni = 0; ni < 4; ni++)
            #pragma unroll
            for (int e = 0; e < 4; e++) acc[mi][ni][e] = 0.f;

    issueStage(0, 0);
    CP_COMMIT();

    int buf = 0;
    for (int kt = 0; kt < nK; kt++) {
        if (kt + 1 < nK) {
            issueStage(kt + 1, buf ^ 1);
            CP_COMMIT();
            asm volatile("cp.async.wait_group 1;\n");
        } else {
            asm volatile("cp.async.wait_group 0;\n");
        }
        __syncthreads();

        #pragma unroll
        for (int kk = 0; kk < BK; kk += 8) {
            uint32_t af[4][4], bfr[4][2];
            #pragma unroll
            for (int mi = 0; mi < 4; mi++) {
                int mr = wm0 + mi*16 + g;
                af[mi][0] = __float_as_uint(As[buf][mr    ][kk + tig]);
                af[mi][1] = __float_as_uint(As[buf][mr + 8][kk + tig]);
                af[mi][2] = __float_as_uint(As[buf][mr    ][kk + tig + 4]);
                af[mi][3] = __float_as_uint(As[buf][mr + 8][kk + tig + 4]);
            }
            #pragma unroll
            for (int ni = 0; ni < 4; ni++) {
                int nc = wn0 + ni*8 + g;
                bfr[ni][0] = __float_as_uint(Bs[buf][kk + tig][nc]);
                bfr[ni][1] = __float_as_uint(Bs[buf][kk + tig + 4][nc]);
            }
            #pragma unroll
            for (int mi = 0; mi < 4; mi++)
                #pragma unroll
                for (int ni = 0; ni < 4; ni++)
                    mma_tf32(acc[mi][ni], af[mi], bfr[ni]);
        }
        __syncthreads();
        buf ^= 1;
    }

    // ---------------- epilogues (guards use GLOBAL column cbase+col) ---------
    if (MODE == 1) {
        #pragma unroll
        for (int mi = 0; mi < 4; mi++) {
            int mblk = ((m0 + wm0) >> 4) + mi;
            int d = mblk*8 + g;
            float bfv = bias[mblk*16 + g];
            float bgv = bias[mblk*16 + 8 + g];
            size_t zoff = ((size_t)(bb*256 + d))*TFULL + tBase;
            #pragma unroll
            for (int ni = 0; ni < 4; ni++) {
                int col = wn0 + ni*8 + 2*tig;
                #pragma unroll
                for (int e = 0; e < 2; e++) {
                    if (cbase + col + e < tLen) {
                        float f = acc[mi][ni][e]   + bfv;
                        float gg = acc[mi][ni][2+e] + bgv;
                        float z = acc_tanh(f) * fast_sig(gg);
                        float zh = rna(z);
                        O0[zoff + col + e] = zh;
                        O1[zoff + col + e] = rna(z - zh);
                    }
                }
            }
        }
    } else if (MODE == 2) {
        #pragma unroll
        for (int mi = 0; mi < 4; mi++) {
            #pragma unroll
            for (int half = 0; half < 2; half++) {
                int m = m0 + wm0 + mi*16 + g + half*8;
                if (m < 256) {
                    float* srow = skipbuf + ((size_t)(bb*256 + m))*OUTTP;
                    #pragma unroll
                    for (int ni = 0; ni < 4; ni++) {
                        int col = wn0 + ni*8 + 2*tig;
                        #pragma unroll
                        for (int e = 0; e < 2; e++) {
                            int t = tBase + col + e;
                            if (cbase + col + e < tLen && t >= tMin) {
                                int ts = t - 2046;
                                if (ts >= 0) {
                                    float v = acc[mi][ni][half*2 + e];
                                    if (first) srow[ts] = v;
                                    else       srow[ts] += v;
                                }
                            }
                        }
                    }
                } else {
                    size_t off = ((size_t)(bb*384 + (m - 256)))*TFULL + tBase;
                    #pragma unroll
                    for (int ni = 0; ni < 4; ni++) {
                        int col = wn0 + ni*8 + 2*tig;
                        #pragma unroll
                        for (int e = 0; e < 2; e++) {
                            int t = tBase + col + e;
                            if (cbase + col + e < tLen && t >= tMin) {
                                float xo = X2h[off + col + e] + X2l[off + col + e];
                                float v = acc[mi][ni][half*2 + e] + xo;
                                float vh = rna(v);
                                O0[off + col + e] = vh;
                                O1[off + col + e] = rna(v - vh);
                            }
                        }
                    }
                }
            }
        }
    } else {  // MODE 0 (split out) / MODE 3 (relu, single out)
        #pragma unroll
        for (int mi = 0; mi < 4; mi++) {
            #pragma unroll
            for (int half = 0; half < 2; half++) {
                int m = m0 + wm0 + mi*16 + g + half*8;
                float bv = bias[m];
                size_t off;
                if (MODE == 0) off = ((size_t)(bb*384 + m))*TFULL + tBase;
                else           off = ((size_t)(bb*512 + m))*OUTTP + tBase;
                #pragma unroll
                for (int ni = 0; ni < 4; ni++) {
                    int col = wn0 + ni*8 + 2*tig;
                    #pragma unroll
                    for (int e = 0; e < 2; e++) {
                        if (cbase + col + e < tLen) {
                            float v = acc[mi][ni][half*2 + e] + bv;
                            if (MODE == 3) {
                                O0[off + col + e] = fmaxf(v, 0.f);
                            } else {
                                float vh = rna(v);
                                O0[off + col + e] = vh;
                                O1[off + col + e] = rna(v - vh);
                            }
                        }
                    }
                }
            }
        }
    }
}

// ---------------- post2 + log_softmax ----------------------------------------
__global__ __launch_bounds__(256) void post2_softmax(const float* __restrict__ H,
                                                     const float* __restrict__ W2,
                                                     const float* __restrict__ B2,
                                                     float* __restrict__ out)
{
    int b = blockIdx.y;
    int t0 = blockIdx.x * 16;
    int q = threadIdx.x;                 // 0..255
    __shared__ float Hs[512*16];
    __shared__ float Ws[256*16];

    for (int idx = q; idx < 512*16; idx += 256) {
        int p = idx >> 4, j = idx & 15;
        int t = t0 + j;
        Hs[idx] = (t < OUTT) ? H[((size_t)(b*512 + p))*OUTTP + t] : 0.f;
    }
    float acc[16];
    float bq = B2[q];
    #pragma unroll
    for (int j = 0; j < 16; j++) acc[j] = bq;

    for (int p0 = 0; p0 < 512; p0 += 16) {
        __syncthreads();
        for (int idx = q; idx < 256*16; idx += 256) {
            int qq = idx >> 4, pp = idx & 15;
            Ws[idx] = W2[(size_t)qq*512 + p0 + pp];
        }
        __syncthreads();
        #pragma unroll
        for (int pp = 0; pp < 16; pp++) {
            float w = Ws[q*16 + pp];
            const float* hp = &Hs[(p0 + pp)*16];
            #pragma unroll
            for (int j = 0; j < 16; j++) acc[j] += w * hp[j];
        }
    }
    __syncthreads();
    #pragma unroll
    for (int j = 0; j < 16; j++) Hs[q*16 + j] = acc[j];
    __syncthreads();
    if (q < 16) {
        float mx = -1e30f;
        for (int qq = 0; qq < 256; qq++) mx = fmaxf(mx, Hs[qq*16 + q]);
        float s = 0.f;
        for (int qq = 0; qq < 256; qq++) s += expf(Hs[qq*16 + q] - mx);
        Ws[q] = mx + logf(s);
    }
    __syncthreads();
    #pragma unroll
    for (int j = 0; j < 16; j++) {
        int t = t0 + j;
        if (t < OUTT) out[((size_t)(b*256 + q))*OUTT + t] = acc[j] - Ws[j];
    }
}

// ---------------- host --------------------------------------------------------
static const int h_dils[20] = {1,2,4,8,16,32,64,128,256,512,1,2,4,8,16,32,64,128,256,512};

extern "C" void kernel_launch(void* const* d_in, const int* in_sizes, int n_in,
                              void* d_out, int out_size)
{
    (void)in_sizes; (void)n_in; (void)out_size;
    const float* wav       = (const float*)d_in[0];
    const float* lc_sparse = (const float*)d_in[1];
    const float* lc_conv_w = (const float*)d_in[2];
    const float* lc_conv_b = (const float*)d_in[3];
    const float* ups_w0    = (const float*)d_in[4];
    const float* ups_b0    = (const float*)d_in[5];
    const float* ups_w1    = (const float*)d_in[6];
    const float* ups_b1    = (const float*)d_in[7];
    const float* ups_w2    = (const float*)d_in[8];
    const float* ups_b2    = (const float*)d_in[9];
    const float* ups_w3    = (const float*)d_in[10];
    const float* ups_b3    = (const float*)d_in[11];
    const float* emb_w     = (const float*)d_in[12];
    const float* emb_b     = (const float*)d_in[13];
    const float* base_w    = (const float*)d_in[14];
    const float* base_b    = (const float*)d_in[15];
    const float* sig_w     = (const float*)d_in[16];
    const float* sig_b     = (const float*)d_in[17];
    const float* gate_w    = (const float*)d_in[18];
    const float* gate_b    = (const float*)d_in[19];
    const float* psig_w    = (const float*)d_in[20];
    const float* pgate_w   = (const float*)d_in[21];
    const float* skp_w     = (const float*)d_in[22];
    const float* res_w     = (const float*)d_in[23];
    const float* post1_w   = (const float*)d_in[24];
    const float* post1_b   = (const float*)d_in[25];
    const float* post2_w   = (const float*)d_in[26];
    const float* post2_b   = (const float*)d_in[27];
    const int*   spk       = (const int*)d_in[28];
    const int*   jit       = (const int*)d_in[29];
    float* out = (float*)d_out;

    float *pXh0r,*pXl0r,*pXh1r,*pXl1r,*pCh,*pCl,*pCF,*pZh,*pZl,*pWh,*pWl;
    float *pSkip,*pSkh,*pSkl,*pH,*pWcat,*pWB,*pWbA,*pWp1,*pfb,*pLc1,*pUpA,*pUpB;
    cudaGetSymbolAddress((void**)&pXh0r, g_Xh0);
    cudaGetSymbolAddress((void**)&pXl0r, g_Xl0);
    cudaGetSymbolAddress((void**)&pXh1r, g_Xh1);
    cudaGetSymbolAddress((void**)&pXl1r, g_Xl1);
    cudaGetSymbolAddress((void**)&pCh,   g_condh);
    cudaGetSymbolAddress((void**)&pCl,   g_condl);
    cudaGetSymbolAddress((void**)&pCF,   g_condF);
    cudaGetSymbolAddress((void**)&pZh,   g_Zh);
    cudaGetSymbolAddress((void**)&pZl,   g_Zl);
    cudaGetSymbolAddress((void**)&pWh,   g_wavh);
    cudaGetSymbolAddress((void**)&pWl,   g_wavl);
    cudaGetSymbolAddress((void**)&pSkip, g_skip);
    cudaGetSymbolAddress((void**)&pSkh,  g_skh);
    cudaGetSymbolAddress((void**)&pSkl,  g_skl);
    cudaGetSymbolAddress((void**)&pH,    g_H);
    cudaGetSymbolAddress((void**)&pWcat, g_Wcat);
    cudaGetSymbolAddress((void**)&pWB,   g_WB);
    cudaGetSymbolAddress((void**)&pWbA,  g_WbA);
    cudaGetSymbolAddress((void**)&pWp1,  g_Wp1);
    cudaGetSymbolAddress((void**)&pfb,   g_fb);
    cudaGetSymbolAddress((void**)&pLc1,  g_lc1);
    cudaGetSymbolAddress((void**)&pUpA,  g_upA);
    cudaGetSymbolAddress((void**)&pUpB,  g_upB);
    float* pXh0 = pXh0r + LEAD;  float* pXl0 = pXl0r + LEAD;
    float* pXh1 = pXh1r + LEAD;  float* pXl1 = pXl1r + LEAD;

    {
        int n = 20*512*3072;
        pack_weights<<<(n + 255)/256, 256>>>(sig_w, sig_b, gate_w, gate_b,
                                             psig_w, pgate_w, skp_w, res_w,
                                             base_w, post1_w);
    }
    {   // wav -> hi/lo
        int n = 4*256*TFULL;
        split_flat<<<(n + 255)/256, 256>>>(wav, pWh, pWl, n, 0);
    }

    // conditioning path
    lc1_kernel<<<dim3(128, 4), 64>>>(lc_sparse, jit, lc_conv_w, lc_conv_b);
    tconv_kernel<<<dim3((290+127)/128, 128, 4), 128>>>(pLc1, ups_w0, ups_b0, pUpA,
        62, 290, 25, 5, 62, 128*62, 290, 128*290);
    tconv_kernel<<<dim3((1148+127)/128, 128, 4), 128>>>(pUpA, ups_w1, ups_b1, pUpB,
        290, 1148, 16, 4, 290, 128*290, 1148, 128*1148);
    tconv_kernel<<<dim3((4580+127)/128, 128, 4), 128>>>(pUpB, ups_w2, ups_b2, pUpA,
        1148, 4580, 16, 4, 1148, 128*1148, 4580, 128*4580);
    tconv_kernel<<<dim3((TFULL+127)/128, 128, 4), 128>>>(pUpA, ups_w3, ups_b3, pCF,
        4580, TFULL, 16, 4, 4580, 128*4580, TFULL, 128*TFULL);
    {
        int n = 4*128*TFULL;
        split_cond<<<(n + 255)/256, 256>>>(pCF, pCh, pCl);
    }
    gc_kernel<<<dim3((TFULL+255)/256, 128, 4), 256>>>(emb_w, emb_b, spk, pCh, pCl);

    // base 1x1 conv -> X0 (split)
    gemm_tc<0><<<dim3((TFULL+127)/128, 3, 4), 256>>>(pWbA, pWh, pWl, nullptr, nullptr,
        base_b, pXh0, pXl0, nullptr, nullptr, nullptr, 0, TFULL, 0, 0, 0);

    // 20 residual layers (column origin aligned down to multiple of 4)
    int cum = 0;
    for (int i = 0; i < 20; i++) {
        int dil = h_dils[i];
        int cl = cum + dil;
        int tA = cl & ~3;
        int tLen = TFULL - tA;
        float* Xih = (i % 2 == 0) ? pXh0 : pXh1;  float* Xil = (i % 2 == 0) ? pXl0 : pXl1;
        float* Xoh = (i % 2 == 0) ? pXh1 : pXh0;  float* Xol = (i % 2 == 0) ? pXl1 : pXl0;
        int gx = (tLen + 127)/128;
        gemm_tc<1><<<dim3(gx, 4, 4), 256>>>(pWcat + (size_t)i*512*3072, Xih, Xil, pCh, pCl,
            pfb + i*512, pZh, pZl, nullptr, nullptr, nullptr, tA, tLen, dil, 0, cl);
        gemm_tc<2><<<dim3(gx, 5, 4), 256>>>(pWB + (size_t)i*640*768, pZh, pZl, nullptr, nullptr,
            nullptr, Xoh, Xol, Xih, Xil, pSkip, tA, tLen, 0, (i == 0) ? 1 : 0, cl);
        cum = cl;
    }

    {   // relu(skip) -> hi/lo
        int n = 4*256*OUTTP;
        split_flat<<<(n + 255)/256, 256>>>(pSkip, pSkh, pSkl, n, 1);
    }
    gemm_tc<3><<<dim3((OUTT+127)/128, 4, 4), 256>>>(pWp1, pSkh, pSkl, nullptr, nullptr,
        post1_b, pH, nullptr, nullptr, nullptr, nullptr, 0, OUTT, 0, 0, 0);
    post2_softmax<<<dim3((OUTT+15)/16, 4), 256>>>(pH, post2_w, post2_b, out);
}

// round 9
// speedup vs baseline: 1.8923x; 1.6909x over previous
#include <cuda_runtime.h>
#include <cuda_bf16.h>
#include <cstdint>
#include <math.h>

// ----------------------------------------------------------------------------
// WaveNet on GB300/B200 — round 8: bf16 3-term compensated mma.sync GEMMs
// (m16n8k16) with ldmatrix operand loading.
//   A·B ≈ Ah·Bh + Al·Bh + Ah·Bl ; A' = [Wh|Wl|Wh] bf16, B' = [Bh;Bh;Bl] bf16.
//   Activations as bf16 (hi,lo) planes, row stride TP=18312 (16B-aligned rows).
//   B=4, T=18308, 20 layers, dils [1..512]x2, TOTAL_LW=2046, OUTT=16262
// ----------------------------------------------------------------------------

#define TFULL 18308
#define TP    18312      // padded bf16 plane row stride (mult of 8)
#define OUTT  16262
#define OUTTP 16264      // padded row stride for skip/H
#define SLACK 4096
#define LEAD  64

#define XPE   (4u*384u*18312u)
#define CPE   (4u*256u*18312u)
#define SPE   (4u*256u*16264u)

typedef __nv_bfloat16 bf16;

// ---------------- scratch (device globals: allocation-free, zero-init) ------
__device__ __align__(128) bf16  g_Xh0[XPE + SLACK + LEAD];
__device__ __align__(128) bf16  g_Xl0[XPE + SLACK + LEAD];
__device__ __align__(128) bf16  g_Xh1[XPE + SLACK + LEAD];
__device__ __align__(128) bf16  g_Xl1[XPE + SLACK + LEAD];
__device__ __align__(128) bf16  g_Xsh[XPE + SLACK + LEAD];   // X shifted by 1 (dil=1 layers)
__device__ __align__(128) bf16  g_Xsl[XPE + SLACK + LEAD];
__device__ __align__(128) bf16  g_condh[CPE + SLACK];
__device__ __align__(128) bf16  g_condl[CPE + SLACK];
__device__ __align__(128) float g_condF[4u*128u*18308u];
__device__ __align__(128) bf16  g_Zh[CPE + SLACK];
__device__ __align__(128) bf16  g_Zl[CPE + SLACK];
__device__ __align__(128) bf16  g_wavh[CPE + SLACK];
__device__ __align__(128) bf16  g_wavl[CPE + SLACK];
__device__ __align__(128) float g_skip[SPE + SLACK];
__device__ __align__(128) bf16  g_skh[SPE + SLACK];
__device__ __align__(128) bf16  g_skl[SPE + SLACK];
__device__ __align__(128) float g_H[4u*512u*16264u + SLACK];
__device__ __align__(128) bf16  g_Wcat[20u*512u*3072u];  // [Wh|Wl|Wh], 16-row filt/gate interleave
__device__ __align__(128) bf16  g_WB[20u*640u*768u];     // [Wh|Wl|Wh]; rows 0..255 skip, 256..639 res
__device__ __align__(128) bf16  g_WbA[384u*768u];
__device__ __align__(128) bf16  g_Wp1[512u*768u];
__device__ __align__(128) float g_fb[20u*512u];
__device__ __align__(128) float g_lc1[4u*128u*62u];
__device__ __align__(128) float g_upA[4u*128u*4580u];
__device__ __align__(128) float g_upB[4u*128u*4580u];

// ---------------- helpers -----------------------------------------------------
__device__ __forceinline__ uint32_t sptr(const void* p) {
    return (uint32_t)__cvta_generic_to_shared(p);
}
#define CP16(dst, src) \
    asm volatile("cp.async.cg.shared.global [%0], [%1], 16;\n" :: "r"(dst), "l"(src))
#define CP8(dst, src) \
    asm volatile("cp.async.ca.shared.global [%0], [%1], 8;\n" :: "r"(dst), "l"(src))
#define CP4(dst, src) \
    asm volatile("cp.async.ca.shared.global [%0], [%1], 4;\n" :: "r"(dst), "l"(src))
#define CP_COMMIT() asm volatile("cp.async.commit_group;\n")

__device__ __forceinline__ void mma_bf16(float c[4], const uint32_t a[4], const uint32_t b[2]) {
    asm volatile(
        "mma.sync.aligned.m16n8k16.row.col.f32.bf16.bf16.f32 "
        "{%0,%1,%2,%3}, {%4,%5,%6,%7}, {%8,%9}, {%0,%1,%2,%3};"
        : "+f"(c[0]), "+f"(c[1]), "+f"(c[2]), "+f"(c[3])
        : "r"(a[0]), "r"(a[1]), "r"(a[2]), "r"(a[3]), "r"(b[0]), "r"(b[1]));
}
#define LDSM_X4(r0,r1,r2,r3,addr) \
    asm volatile("ldmatrix.sync.aligned.m8n8.x4.shared.b16 {%0,%1,%2,%3}, [%4];" \
        : "=r"(r0), "=r"(r1), "=r"(r2), "=r"(r3) : "r"(addr))
#define LDSM_X4T(r0,r1,r2,r3,addr) \
    asm volatile("ldmatrix.sync.aligned.m8n8.x4.trans.shared.b16 {%0,%1,%2,%3}, [%4];" \
        : "=r"(r0), "=r"(r1), "=r"(r2), "=r"(r3) : "r"(addr))

__device__ __forceinline__ float fast_sig(float x) {
    float e; asm("ex2.approx.f32 %0, %1;" : "=f"(e) : "f"(-x * 1.4426950408889634f));
    float r; asm("rcp.approx.f32 %0, %1;" : "=f"(r) : "f"(1.f + e));
    return r;
}
__device__ __forceinline__ float acc_tanh(float x) { return 2.f * fast_sig(2.f * x) - 1.f; }
__device__ __forceinline__ void bsplit(float v, bf16& h, bf16& l) {
    h = __float2bfloat16(v);
    l = __float2bfloat16(v - __bfloat162float(h));
}

// ---------------- weight packing (hi|lo|hi augmented, bf16) -------------------
__global__ void pack_weights(const float* __restrict__ sig_w, const float* __restrict__ sig_b,
                             const float* __restrict__ gate_w, const float* __restrict__ gate_b,
                             const float* __restrict__ psig_w, const float* __restrict__ pgate_w,
                             const float* __restrict__ skp_w, const float* __restrict__ res_w,
                             const float* __restrict__ base_w, const float* __restrict__ post1_w)
{
    int idx = blockIdx.x * blockDim.x + threadIdx.x;
    if (idx < 20*512*3072) {
        int l = idx / (512*3072); int r = idx % (512*3072);
        int m = r / 3072;         int kp = r % 3072;
        int sel = kp >> 10;       int k = kp & 1023;       // 0:hi 1:lo 2:hi
        int blk = m >> 4;         int rr = m & 15;
        int d = blk*8 + (rr & 7); int gte = rr >> 3;
        const float* ws = gte ? gate_w : sig_w;
        const float* wp = gte ? pgate_w : psig_w;
        float v;
        if (k < 384)       v = ws[((size_t)(l*256 + d)*384 + k)*2 + 0];
        else if (k < 768)  v = ws[((size_t)(l*256 + d)*384 + (k-384))*2 + 1];
        else               v = wp[(size_t)(l*256 + d)*256 + (k-768)];
        bf16 h, lo; bsplit(v, h, lo);
        g_Wcat[idx] = (sel == 1) ? lo : h;
    }
    if (idx < 20*640*768) {
        int l = idx / (640*768); int r = idx % (640*768);
        int m = r / 768;         int kp = r % 768;
        int sel = kp >> 8;       int k = kp & 255;
        float v = (m < 256) ? skp_w[(size_t)(l*256 + m)*256 + k]
                            : res_w[(size_t)(l*384 + (m-256))*256 + k];
        bf16 h, lo; bsplit(v, h, lo);
        g_WB[idx] = (sel == 1) ? lo : h;
    }
    if (idx < 384*768) {
        int m = idx / 768; int kp = idx % 768;
        int sel = kp >> 8; int k = kp & 255;
        bf16 h, lo; bsplit(base_w[m*256 + k], h, lo);
        g_WbA[idx] = (sel == 1) ? lo : h;
    }
    if (idx < 512*768) {
        int m = idx / 768; int kp = idx % 768;
        int sel = kp >> 8; int k = kp & 255;
        bf16 h, lo; bsplit(post1_w[m*256 + k], h, lo);
        g_Wp1[idx] = (sel == 1) ? lo : h;
    }
    if (idx < 20*512) {
        int l = idx / 512; int m = idx % 512;
        int blk = m >> 4;  int rr = m & 15;
        int d = blk*8 + (rr & 7); int gte = rr >> 3;
        g_fb[idx] = gte ? gate_b[l*256 + d] : sig_b[l*256 + d];
    }
}

// ---------------- split / shift kernels ---------------------------------------
// fp32 [R][Tin] (contig) -> bf16 planes [R][TPout]
__global__ void split_plane(const float* __restrict__ src, bf16* __restrict__ h,
                            bf16* __restrict__ l, int R, int Tin, int TPout, int do_relu)
{
    int i = blockIdx.x * blockDim.x + threadIdx.x;
    if (i < R * Tin) {
        int t = i % Tin; int rr = i / Tin;
        float v = src[i];
        if (do_relu) v = fmaxf(v, 0.f);
        bf16 hh, ll; bsplit(v, hh, ll);
        size_t o = (size_t)rr * TPout + t;
        h[o] = hh; l[o] = ll;
    }
}
// cond fp32 [4][128][TFULL] -> planes rows (b*256+c), stride TP
__global__ void split_cond(const float* __restrict__ src, bf16* __restrict__ h,
                           bf16* __restrict__ l)
{
    int i = blockIdx.x * blockDim.x + threadIdx.x;
    const int n = 4*128*TFULL;
    if (i < n) {
        int t = i % TFULL; int rc = i / TFULL;
        int c = rc & 127;  int b = rc >> 7;
        bf16 hh, ll; bsplit(src[i], hh, ll);
        size_t o = ((size_t)(b*256) + c)*TP + t;
        h[o] = hh; l[o] = ll;
    }
}
// Xs[t] = X[t-1]
__global__ void shift1(const bf16* __restrict__ Xh, const bf16* __restrict__ Xl,
                       bf16* __restrict__ Sh, bf16* __restrict__ Sl)
{
    int i = blockIdx.x * blockDim.x + threadIdx.x;
    const int n = 4*384*TP;
    if (i < n) {
        int t = i % TP; size_t row = (size_t)(i / TP) * TP;
        bool ok = (t >= 1) && (t - 1 < TFULL);
        Sh[row + t] = ok ? Xh[row + t - 1] : __float2bfloat16(0.f);
        Sl[row + t] = ok ? Xl[row + t - 1] : __float2bfloat16(0.f);
    }
}

// ---------------- conditioning path (fp32, unchanged) -------------------------
__global__ void lc1_kernel(const float* __restrict__ lc_sparse, const int* __restrict__ jit,
                           const float* __restrict__ w, const float* __restrict__ bias)
{
    int o = blockIdx.x, b = blockIdx.y;
    int tx = threadIdx.x;               // 64 threads
    __shared__ int   js[64];
    __shared__ float lcs[64][65];
    js[tx] = jit[b*64 + tx];
    __syncthreads();
    for (int s = 0; s < 64; s++)
        lcs[tx][s] = lc_sparse[(size_t)(b*64 + tx)*64 + js[s]];
    __syncthreads();
    if (tx < 62) {
        float acc = bias[o];
        for (int c = 0; c < 64; c++) {
            const float* wr = &w[(size_t)(o*64 + c)*3];
            acc += wr[0]*lcs[c][tx] + wr[1]*lcs[c][tx+1] + wr[2]*lcs[c][tx+2];
        }
        g_lc1[(size_t)(b*128 + o)*62 + tx] = acc;
    }
}

__global__ void tconv_kernel(const float* __restrict__ in, const float* __restrict__ w,
                             const float* __restrict__ bias, float* __restrict__ out,
                             int Lin, int Lout, int Kk, int S,
                             int inCh, int inB, int outCh, int outB)
{
    int t = blockIdx.x * blockDim.x + threadIdx.x;
    int o = blockIdx.y, b = blockIdx.z;
    if (t >= Lout) return;
    int r = (S - 1 - t) % S; if (r < 0) r += S;
    int u0 = (t + r - S + 1) / S;
    int jmax = (Kk - r + S - 1) / S;
    int jlim = Lin - u0; if (jlim < jmax) jmax = jlim;
    float acc = bias[o];
    for (int a = 0; a < 128; a++) {
        const float* inr = in + (size_t)b*inB + (size_t)a*inCh + u0;
        const float* wr  = w + (size_t)(a*128 + o)*Kk + (Kk - 1 - r);
        for (int j = 0; j < jmax; j++)
            acc += inr[j] * wr[-j*S];
    }
    out[(size_t)b*outB + (size_t)o*outCh + t] = acc;
}

__global__ void gc_kernel(const float* __restrict__ emb_w, const float* __restrict__ emb_b,
                          const int* __restrict__ spk,
                          bf16* __restrict__ ch, bf16* __restrict__ clo)
{
    int t = blockIdx.x * blockDim.x + threadIdx.x;
    int c = blockIdx.y, b = blockIdx.z;
    if (t < TFULL) {
        float v = emb_w[c*40 + spk[b]] + emb_b[c];
        bf16 h, l; bsplit(v, h, l);
        size_t o = ((size_t)(b*256) + 128 + c)*TP + t;
        ch[o] = h; clo[o] = l;
    }
}

// ---------------- bf16 3-term tensor-core fused GEMM (augmented K) ------------
// 128x128 tile, BK=32, 256 threads (8 warps 2x4), warp tile 64x32, m16n8k16.
// K' = 3*KB; B' chunks: [0,KB)=hi, [KB,2KB)=hi, [2KB,3KB)=lo.
// MODE 0: base   K'=768   X planes = split(W·wav + b)
// MODE 1: layerA K'=3072  Z planes = split(tanh(f)·sig(g))   [16-row interleave]
// MODE 2: layerB K'=768   skip(fp32) accum + X residual split
// MODE 3: post1  K'=768   H(fp32) = relu(W·skR + b)
template<int MODE>
__global__ __launch_bounds__(256, 2) void gemm_tc(
    const bf16* __restrict__ W,
    const bf16* __restrict__ S0h, const bf16* __restrict__ S0l,
    const bf16* __restrict__ Sdh, const bf16* __restrict__ Sdl,
    const bf16* __restrict__ S1h, const bf16* __restrict__ S1l,
    const float* __restrict__ bias,
    bf16* __restrict__ O0b, bf16* __restrict__ O1b,
    float* __restrict__ O0f,
    const bf16* __restrict__ X2h, const bf16* __restrict__ X2l,
    float* __restrict__ skipbuf,
    int tStart, int tLen, int first, int tMin)
{
    constexpr int KB = (MODE == 1) ? 1024 : 256;
    constexpr int K  = 3 * KB;
    constexpr int BM = 128, BN = 128, BK = 32;
    constexpr int nK = K / BK;
    constexpr int SIN = (MODE == 3) ? OUTTP : TP;
    __shared__ __align__(16) bf16 As[2][BM][40];    // [m][k], stride 40 bf16 (80B)
    __shared__ __align__(16) bf16 Bs[2][BK][136];   // [k][n], stride 136 bf16 (272B)

    const int tid  = threadIdx.x;
    const int lane = tid & 31, warp = tid >> 5;
    const int g    = lane >> 2, tig = lane & 3;
    const int wm0  = (warp >> 2) * 64, wn0 = (warp & 3) * 32;
    const int bx = blockIdx.x, m0 = blockIdx.y * BM, bb = blockIdx.z;
    const int tBase = tStart + bx * BN;
    const int cbase = bx * BN;
    const int l15 = lane & 15, lhi = (lane >> 4) << 3;   // ldmatrix addressing

    const int ar = tid >> 1, acS = (tid & 1) * 16;   // A: row ar, 2x16B at cols acS, acS+8
    const int br = tid >> 4, bc = (tid & 15) * 8;    // B: rows br, br+16; col bc (8 elems=16B)

    auto rowptr = [&](int k) -> const bf16* {
        bool lo = (k >= 2*KB);
        int kk = (k >= 2*KB) ? (k - 2*KB) : ((k >= KB) ? (k - KB) : k);
        if (MODE == 1) {
            if (kk < 384) {
                const bf16* Xs = lo ? Sdl : Sdh;   // pre-shifted by dil
                return Xs + ((size_t)(bb*384 + kk))*TP + tBase;
            } else if (kk < 768) {
                const bf16* Xs = lo ? S0l : S0h;
                return Xs + ((size_t)(bb*384 + (kk-384)))*TP + tBase;
            } else {
                const bf16* Cs = lo ? S1l : S1h;
                return Cs + ((size_t)(bb*256 + (kk-768)))*TP + tBase;
            }
        } else {
            const bf16* Ss = lo ? S0l : S0h;
            return Ss + ((size_t)(bb*256 + kk))*SIN + tBase;
        }
    };
    auto cpB = [&](uint32_t dst, const bf16* p) {
        uintptr_t a = (uintptr_t)p;
        if ((a & 15) == 0) {
            CP16(dst, p);
        } else if ((a & 7) == 0) {
            CP8(dst, p); CP8(dst + 8, p + 4);
        } else {  // 4B-aligned (dil=2 case)
            CP4(dst, p); CP4(dst + 4, p + 2); CP4(dst + 8, p + 4); CP4(dst + 12, p + 6);
        }
    };
    auto issueStage = [&](int kt, int s) {
        const bf16* asrc = W + (size_t)(m0 + ar) * K + kt * BK + acS;
        uint32_t ad = sptr(&As[s][ar][acS]);
        CP16(ad,      asrc);
        CP16(ad + 16, asrc + 8);
        cpB(sptr(&Bs[s][br][bc]),      rowptr(kt*BK + br)      + bc);
        cpB(sptr(&Bs[s][br + 16][bc]), rowptr(kt*BK + br + 16) + bc);
    };

    float acc[4][4][4];
    #pragma unroll
    for (int mi = 0; mi < 4; mi++)
        #pragma unroll
        for (int ni = 0; ni < 4; ni++)
            #pragma unroll
            for (int e = 0; e < 4; e++) acc[mi][ni][e] = 0.f;

    issueStage(0, 0);
    CP_COMMIT();

    int buf = 0;
    for (int kt = 0; kt < nK; kt++) {
        if (kt + 1 < nK) {
            issueStage(kt + 1, buf ^ 1);
            CP_COMMIT();
            asm volatile("cp.async.wait_group 1;\n");
        } else {
            asm volatile("cp.async.wait_group 0;\n");
        }
        __syncthreads();

        #pragma unroll
        for (int kk = 0; kk < BK; kk += 16) {
            uint32_t a[4][4], b[4][2];
            #pragma unroll
            for (int mi = 0; mi < 4; mi++) {
                uint32_t ad = sptr(&As[buf][wm0 + mi*16 + l15][kk + lhi]);
                LDSM_X4(a[mi][0], a[mi][1], a[mi][2], a[mi][3], ad);
            }
            #pragma unroll
            for (int n2 = 0; n2 < 2; n2++) {
                uint32_t bd = sptr(&Bs[buf][kk + l15][wn0 + n2*16 + lhi]);
                LDSM_X4T(b[n2*2][0], b[n2*2][1], b[n2*2+1][0], b[n2*2+1][1], bd);
            }
            #pragma unroll
            for (int mi = 0; mi < 4; mi++)
                #pragma unroll
                for (int ni = 0; ni < 4; ni++)
                    mma_bf16(acc[mi][ni], a[mi], b[ni]);
        }
        __syncthreads();
        buf ^= 1;
    }

    // ---------------- epilogues (global-column guards) ------------------------
    if (MODE == 1) {
        #pragma unroll
        for (int mi = 0; mi < 4; mi++) {
            int mblk = ((m0 + wm0) >> 4) + mi;
            int d = mblk*8 + g;
            float bfv = bias[mblk*16 + g];
            float bgv = bias[mblk*16 + 8 + g];
            size_t zoff = ((size_t)(bb*256 + d))*TP + tBase;
            #pragma unroll
            for (int ni = 0; ni < 4; ni++) {
                int col = wn0 + ni*8 + 2*tig;
                #pragma unroll
                for (int e = 0; e < 2; e++) {
                    if (cbase + col + e < tLen) {
                        float f  = acc[mi][ni][e]   + bfv;
                        float gg = acc[mi][ni][2+e] + bgv;
                        float z = acc_tanh(f) * fast_sig(gg);
                        bf16 zh, zl; bsplit(z, zh, zl);
                        O0b[zoff + col + e] = zh;
                        O1b[zoff + col + e] = zl;
                    }
                }
            }
        }
    } else if (MODE == 2) {
        #pragma unroll
        for (int mi = 0; mi < 4; mi++) {
            #pragma unroll
            for (int half = 0; half < 2; half++) {
                int m = m0 + wm0 + mi*16 + g + half*8;
                if (m < 256) {
                    float* srow = skipbuf + ((size_t)(bb*256 + m))*OUTTP;
                    #pragma unroll
                    for (int ni = 0; ni < 4; ni++) {
                        int col = wn0 + ni*8 + 2*tig;
                        #pragma unroll
                        for (int e = 0; e < 2; e++) {
                            int t = tBase + col + e;
                            if (cbase + col + e < tLen && t >= tMin) {
                                int ts = t - 2046;
                                if (ts >= 0) {
                                    float v = acc[mi][ni][half*2 + e];
                                    if (first) srow[ts] = v;
                                    else       srow[ts] += v;
                                }
                            }
                        }
                    }
                } else {
                    size_t off = ((size_t)(bb*384 + (m - 256)))*TP + tBase;
                    #pragma unroll
                    for (int ni = 0; ni < 4; ni++) {
                        int col = wn0 + ni*8 + 2*tig;
                        #pragma unroll
                        for (int e = 0; e < 2; e++) {
                            int t = tBase + col + e;
                            if (cbase + col + e < tLen && t >= tMin) {
                                float xo = __bfloat162float(X2h[off + col + e])
                                         + __bfloat162float(X2l[off + col + e]);
                                float v = acc[mi][ni][half*2 + e] + xo;
                                bf16 vh, vl; bsplit(v, vh, vl);
                                O0b[off + col + e] = vh;
                                O1b[off + col + e] = vl;
                            }
                        }
                    }
                }
            }
        }
    } else {  // MODE 0 (split bf16 out) / MODE 3 (fp32 relu out)
        #pragma unroll
        for (int mi = 0; mi < 4; mi++) {
            #pragma unroll
            for (int half = 0; half < 2; half++) {
                int m = m0 + wm0 + mi*16 + g + half*8;
                float bv = bias[m];
                size_t off;
                if (MODE == 0) off = ((size_t)(bb*384 + m))*TP + tBase;
                else           off = ((size_t)(bb*512 + m))*OUTTP + tBase;
                #pragma unroll
                for (int ni = 0; ni < 4; ni++) {
                    int col = wn0 + ni*8 + 2*tig;
                    #pragma unroll
                    for (int e = 0; e < 2; e++) {
                        if (cbase + col + e < tLen) {
                            float v = acc[mi][ni][half*2 + e] + bv;
                            if (MODE == 3) {
                                O0f[off + col + e] = fmaxf(v, 0.f);
                            } else {
                                bf16 vh, vl; bsplit(v, vh, vl);
                                O0b[off + col + e] = vh;
                                O1b[off + col + e] = vl;
                            }
                        }
                    }
                }
            }
        }
    }
}

// ---------------- post2 + log_softmax ----------------------------------------
__global__ __launch_bounds__(256) void post2_softmax(const float* __restrict__ H,
                                                     const float* __restrict__ W2,
                                                     const float* __restrict__ B2,
                                                     float* __restrict__ out)
{
    int b = blockIdx.y;
    int t0 = blockIdx.x * 16;
    int q = threadIdx.x;                 // 0..255
    __shared__ float Hs[512*16];
    __shared__ float Ws[256*16];

    for (int idx = q; idx < 512*16; idx += 256) {
        int p = idx >> 4, j = idx & 15;
        int t = t0 + j;
        Hs[idx] = (t < OUTT) ? H[((size_t)(b*512 + p))*OUTTP + t] : 0.f;
    }
    float acc[16];
    float bq = B2[q];
    #pragma unroll
    for (int j = 0; j < 16; j++) acc[j] = bq;

    for (int p0 = 0; p0 < 512; p0 += 16) {
        __syncthreads();
        for (int idx = q; idx < 256*16; idx += 256) {
            int qq = idx >> 4, pp = idx & 15;
            Ws[idx] = W2[(size_t)qq*512 + p0 + pp];
        }
        __syncthreads();
        #pragma unroll
        for (int pp = 0; pp < 16; pp++) {
            float w = Ws[q*16 + pp];
            const float* hp = &Hs[(p0 + pp)*16];
            #pragma unroll
            for (int j = 0; j < 16; j++) acc[j] += w * hp[j];
        }
    }
    __syncthreads();
    #pragma unroll
    for (int j = 0; j < 16; j++) Hs[q*16 + j] = acc[j];
    __syncthreads();
    if (q < 16) {
        float mx = -1e30f;
        for (int qq = 0; qq < 256; qq++) mx = fmaxf(mx, Hs[qq*16 + q]);
        float s = 0.f;
        for (int qq = 0; qq < 256; qq++) s += expf(Hs[qq*16 + q] - mx);
        Ws[q] = mx + logf(s);
    }
    __syncthreads();
    #pragma unroll
    for (int j = 0; j < 16; j++) {
        int t = t0 + j;
        if (t < OUTT) out[((size_t)(b*256 + q))*OUTT + t] = acc[j] - Ws[j];
    }
}

// ---------------- host --------------------------------------------------------
static const int h_dils[20] = {1,2,4,8,16,32,64,128,256,512,1,2,4,8,16,32,64,128,256,512};

extern "C" void kernel_launch(void* const* d_in, const int* in_sizes, int n_in,
                              void* d_out, int out_size)
{
    (void)in_sizes; (void)n_in; (void)out_size;
    const float* wav       = (const float*)d_in[0];
    const float* lc_sparse = (const float*)d_in[1];
    const float* lc_conv_w = (const float*)d_in[2];
    const float* lc_conv_b = (const float*)d_in[3];
    const float* ups_w0    = (const float*)d_in[4];
    const float* ups_b0    = (const float*)d_in[5];
    const float* ups_w1    = (const float*)d_in[6];
    const float* ups_b1    = (const float*)d_in[7];
    const float* ups_w2    = (const float*)d_in[8];
    const float* ups_b2    = (const float*)d_in[9];
    const float* ups_w3    = (const float*)d_in[10];
    const float* ups_b3    = (const float*)d_in[11];
    const float* emb_w     = (const float*)d_in[12];
    const float* emb_b     = (const float*)d_in[13];
    const float* base_w    = (const float*)d_in[14];
    const float* base_b    = (const float*)d_in[15];
    const float* sig_w     = (const float*)d_in[16];
    const float* sig_b     = (const float*)d_in[17];
    const float* gate_w    = (const float*)d_in[18];
    const float* gate_b    = (const float*)d_in[19];
    const float* psig_w    = (const float*)d_in[20];
    const float* pgate_w   = (const float*)d_in[21];
    const float* skp_w     = (const float*)d_in[22];
    const float* res_w     = (const float*)d_in[23];
    const float* post1_w   = (const float*)d_in[24];
    const float* post1_b   = (const float*)d_in[25];
    const float* post2_w   = (const float*)d_in[26];
    const float* post2_b   = (const float*)d_in[27];
    const int*   spk       = (const int*)d_in[28];
    const int*   jit       = (const int*)d_in[29];
    float* out = (float*)d_out;

    bf16 *pXh0r,*pXl0r,*pXh1r,*pXl1r,*pXshr,*pXslr,*pCh,*pCl,*pZh,*pZl,*pWh,*pWl,*pSkh,*pSkl;
    bf16 *pWcat,*pWB,*pWbA,*pWp1;
    float *pCF,*pSkip,*pH,*pfb,*pLc1,*pUpA,*pUpB;
    cudaGetSymbolAddress((void**)&pXh0r, g_Xh0);
    cudaGetSymbolAddress((void**)&pXl0r, g_Xl0);
    cudaGetSymbolAddress((void**)&pXh1r, g_Xh1);
    cudaGetSymbolAddress((void**)&pXl1r, g_Xl1);
    cudaGetSymbolAddress((void**)&pXshr, g_Xsh);
    cudaGetSymbolAddress((void**)&pXslr, g_Xsl);
    cudaGetSymbolAddress((void**)&pCh,   g_condh);
    cudaGetSymbolAddress((void**)&pCl,   g_condl);
    cudaGetSymbolAddress((void**)&pCF,   g_condF);
    cudaGetSymbolAddress((void**)&pZh,   g_Zh);
    cudaGetSymbolAddress((void**)&pZl,   g_Zl);
    cudaGetSymbolAddress((void**)&pWh,   g_wavh);
    cudaGetSymbolAddress((void**)&pWl,   g_wavl);
    cudaGetSymbolAddress((void**)&pSkip, g_skip);
    cudaGetSymbolAddress((void**)&pSkh,  g_skh);
    cudaGetSymbolAddress((void**)&pSkl,  g_skl);
    cudaGetSymbolAddress((void**)&pH,    g_H);
    cudaGetSymbolAddress((void**)&pWcat, g_Wcat);
    cudaGetSymbolAddress((void**)&pWB,   g_WB);
    cudaGetSymbolAddress((void**)&pWbA,  g_WbA);
    cudaGetSymbolAddress((void**)&pWp1,  g_Wp1);
    cudaGetSymbolAddress((void**)&pfb,   g_fb);
    cudaGetSymbolAddress((void**)&pLc1,  g_lc1);
    cudaGetSymbolAddress((void**)&pUpA,  g_upA);
    cudaGetSymbolAddress((void**)&pUpB,  g_upB);
    bf16* pXh0 = pXh0r + LEAD;  bf16* pXl0 = pXl0r + LEAD;
    bf16* pXh1 = pXh1r + LEAD;  bf16* pXl1 = pXl1r + LEAD;
    bf16* pXsh = pXshr + LEAD;  bf16* pXsl = pXslr + LEAD;

    {
        int n = 20*512*3072;
        pack_weights<<<(n + 255)/256, 256>>>(sig_w, sig_b, gate_w, gate_b,
                                             psig_w, pgate_w, skp_w, res_w,
                                             base_w, post1_w);
    }
    {   // wav -> bf16 hi/lo planes (stride TP)
        int n = 4*256*TFULL;
        split_plane<<<(n + 255)/256, 256>>>(wav, pWh, pWl, 4*256, TFULL, TP, 0);
    }

    // conditioning path
    lc1_kernel<<<dim3(128, 4), 64>>>(lc_sparse, jit, lc_conv_w, lc_conv_b);
    tconv_kernel<<<dim3((290+127)/128, 128, 4), 128>>>(pLc1, ups_w0, ups_b0, pUpA,
        62, 290, 25, 5, 62, 128*62, 290, 128*290);
    tconv_kernel<<<dim3((1148+127)/128, 128, 4), 128>>>(pUpA, ups_w1, ups_b1, pUpB,
        290, 1148, 16, 4, 290, 128*290, 1148, 128*1148);
    tconv_kernel<<<dim3((4580+127)/128, 128, 4), 128>>>(pUpB, ups_w2, ups_b2, pUpA,
        1148, 4580, 16, 4, 1148, 128*1148, 4580, 128*4580);
    tconv_kernel<<<dim3((TFULL+127)/128, 128, 4), 128>>>(pUpA, ups_w3, ups_b3, pCF,
        4580, TFULL, 16, 4, 4580, 128*4580, TFULL, 128*TFULL);
    {
        int n = 4*128*TFULL;
        split_cond<<<(n + 255)/256, 256>>>(pCF, pCh, pCl);
    }
    gc_kernel<<<dim3((TFULL+255)/256, 128, 4), 256>>>(emb_w, emb_b, spk, pCh, pCl);

    // base 1x1 conv -> X0 planes
    gemm_tc<0><<<dim3((TFULL+127)/128, 3, 4), 256>>>(pWbA, pWh, pWl,
        nullptr, nullptr, nullptr, nullptr, base_b,
        pXh0, pXl0, nullptr, nullptr, nullptr, nullptr, 0, TFULL, 0, 0);

    // 20 residual layers (column origin aligned down to multiple of 8)
    int cum = 0;
    for (int i = 0; i < 20; i++) {
        int dil = h_dils[i];
        int cl = cum + dil;
        int tA = cl & ~7;
        int tLen = TFULL - tA;
        bf16* Xih = (i % 2 == 0) ? pXh0 : pXh1;  bf16* Xil = (i % 2 == 0) ? pXl0 : pXl1;
        bf16* Xoh = (i % 2 == 0) ? pXh1 : pXh0;  bf16* Xol = (i % 2 == 0) ? pXl1 : pXl0;
        const bf16 *Xdh, *Xdl;
        if (dil == 1) {
            int n = 4*384*TP;
            shift1<<<(n + 255)/256, 256>>>(Xih, Xil, pXsh, pXsl);
            Xdh = pXsh; Xdl = pXsl;
        } else {
            Xdh = Xih - dil; Xdl = Xil - dil;
        }
        int gx = (tLen + 127)/128;
        gemm_tc<1><<<dim3(gx, 4, 4), 256>>>(pWcat + (size_t)i*512*3072,
            Xih, Xil, Xdh, Xdl, pCh, pCl, pfb + i*512,
            pZh, pZl, nullptr, nullptr, nullptr, nullptr, tA, tLen, 0, cl);
        gemm_tc<2><<<dim3(gx, 5, 4), 256>>>(pWB + (size_t)i*640*768,
            pZh, pZl, nullptr, nullptr, nullptr, nullptr, nullptr,
            Xoh, Xol, nullptr, Xih, Xil, pSkip, tA, tLen, (i == 0) ? 1 : 0, cl);
        cum = cl;
    }

    {   // relu(skip) -> bf16 hi/lo planes (stride OUTTP)
        int n = 4*256*OUTTP;
        split_plane<<<(n + 255)/256, 256>>>(pSkip, pSkh, pSkl, 4*256, OUTTP, OUTTP, 1);
    }
    gemm_tc<3><<<dim3((OUTT+127)/128, 4, 4), 256>>>(pWp1, pSkh, pSkl,
        nullptr, nullptr, nullptr, nullptr, post1_b,
        nullptr, nullptr, pH, nullptr, nullptr, nullptr, 0, OUTT, 0, 0);
    post2_softmax<<<dim3((OUTT+15)/16, 4), 256>>>(pH, post2_w, post2_b, out);
}

// round 12
// speedup vs baseline: 2.1399x; 1.1309x over previous
#include <cuda_runtime.h>
#include <cuda_bf16.h>
#include <cstdint>
#include <math.h>

// ----------------------------------------------------------------------------
// WaveNet on GB300/B200 — round 11: resubmit of R9/R10 (infra-only failures;
// content frozen until a measurement exists).
// bf16 3-term mma.sync GEMMs, BK=64, XOR-swizzled conflict-free smem,
// L2-reuse grid order, packed bf16x2 epilogue.
//   A·B ≈ Ah·Bh + Al·Bh + Ah·Bl ; A' = [Wh|Wl|Wh] bf16, B' = [Bh;Bh;Bl] bf16.
//   B=4, T=18308, 20 layers, dils [1..512]x2, TOTAL_LW=2046, OUTT=16262
// ----------------------------------------------------------------------------

#define TFULL 18308
#define TP    18312      // padded bf16 plane row stride (mult of 8)
#define OUTT  16262
#define OUTTP 16264
#define SLACK 4096
#define LEAD  64

#define XPE   (4u*384u*18312u)
#define CPE   (4u*256u*18312u)
#define SPE   (4u*256u*16264u)

typedef __nv_bfloat16 bf16;

// ---------------- scratch (device globals: allocation-free, zero-init) ------
__device__ __align__(128) bf16  g_Xh0[XPE + SLACK + LEAD];
__device__ __align__(128) bf16  g_Xl0[XPE + SLACK + LEAD];
__device__ __align__(128) bf16  g_Xh1[XPE + SLACK + LEAD];
__device__ __align__(128) bf16  g_Xl1[XPE + SLACK + LEAD];
__device__ __align__(128) bf16  g_Xsh[XPE + SLACK + LEAD];   // X shifted by 1 (dil=1)
__device__ __align__(128) bf16  g_Xsl[XPE + SLACK + LEAD];
__device__ __align__(128) bf16  g_condh[CPE + SLACK];
__device__ __align__(128) bf16  g_condl[CPE + SLACK];
__device__ __align__(128) float g_condF[4u*128u*18308u];
__device__ __align__(128) bf16  g_Zh[CPE + SLACK];
__device__ __align__(128) bf16  g_Zl[CPE + SLACK];
__device__ __align__(128) bf16  g_wavh[CPE + SLACK];
__device__ __align__(128) bf16  g_wavl[CPE + SLACK];
__device__ __align__(128) float g_skip[SPE + SLACK];
__device__ __align__(128) bf16  g_skh[SPE + SLACK];
__device__ __align__(128) bf16  g_skl[SPE + SLACK];
__device__ __align__(128) float g_H[4u*512u*16264u + SLACK];
__device__ __align__(128) bf16  g_Wcat[20u*512u*3072u];
__device__ __align__(128) bf16  g_WB[20u*640u*768u];
__device__ __align__(128) bf16  g_WbA[384u*768u];
__device__ __align__(128) bf16  g_Wp1[512u*768u];
__device__ __align__(128) float g_fb[20u*512u];
__device__ __align__(128) float g_lc1[4u*128u*62u];
__device__ __align__(128) float g_upA[4u*128u*4580u];
__device__ __align__(128) float g_upB[4u*128u*4580u];

// ---------------- helpers -----------------------------------------------------
__device__ __forceinline__ uint32_t sptr(const void* p) {
    return (uint32_t)__cvta_generic_to_shared(p);
}
#define CP16(dst, src) \
    asm volatile("cp.async.cg.shared.global [%0], [%1], 16;\n" :: "r"(dst), "l"(src))
#define CP8(dst, src) \
    asm volatile("cp.async.ca.shared.global [%0], [%1], 8;\n" :: "r"(dst), "l"(src))
#define CP4(dst, src) \
    asm volatile("cp.async.ca.shared.global [%0], [%1], 4;\n" :: "r"(dst), "l"(src))
#define CP_COMMIT() asm volatile("cp.async.commit_group;\n")

__device__ __forceinline__ void mma_bf16(float c[4], const uint32_t a[4], const uint32_t b[2]) {
    asm volatile(
        "mma.sync.aligned.m16n8k16.row.col.f32.bf16.bf16.f32 "
        "{%0,%1,%2,%3}, {%4,%5,%6,%7}, {%8,%9}, {%0,%1,%2,%3};"
        : "+f"(c[0]), "+f"(c[1]), "+f"(c[2]), "+f"(c[3])
        : "r"(a[0]), "r"(a[1]), "r"(a[2]), "r"(a[3]), "r"(b[0]), "r"(b[1]));
}
#define LDSM_X4(r0,r1,r2,r3,addr) \
    asm volatile("ldmatrix.sync.aligned.m8n8.x4.shared.b16 {%0,%1,%2,%3}, [%4];" \
        : "=r"(r0), "=r"(r1), "=r"(r2), "=r"(r3) : "r"(addr))
#define LDSM_X4T(r0,r1,r2,r3,addr) \
    asm volatile("ldmatrix.sync.aligned.m8n8.x4.trans.shared.b16 {%0,%1,%2,%3}, [%4];" \
        : "=r"(r0), "=r"(r1), "=r"(r2), "=r"(r3) : "r"(addr))

__device__ __forceinline__ float fast_sig(float x) {
    float e; asm("ex2.approx.f32 %0, %1;" : "=f"(e) : "f"(-x * 1.4426950408889634f));
    float r; asm("rcp.approx.f32 %0, %1;" : "=f"(r) : "f"(1.f + e));
    return r;
}
__device__ __forceinline__ float acc_tanh(float x) { return 2.f * fast_sig(2.f * x) - 1.f; }
__device__ __forceinline__ void bsplit(float v, bf16& h, bf16& l) {
    h = __float2bfloat16(v);
    l = __float2bfloat16(v - __bfloat162float(h));
}
__device__ __forceinline__ uint32_t bpack(bf16 a, bf16 b) {
    uint16_t ua = __bfloat16_as_ushort(a), ub = __bfloat16_as_ushort(b);
    return (uint32_t)ua | ((uint32_t)ub << 16);
}

// ---------------- weight packing (hi|lo|hi augmented, bf16) -------------------
__global__ void pack_weights(const float* __restrict__ sig_w, const float* __restrict__ sig_b,
                             const float* __restrict__ gate_w, const float* __restrict__ gate_b,
                             const float* __restrict__ psig_w, const float* __restrict__ pgate_w,
                             const float* __restrict__ skp_w, const float* __restrict__ res_w,
                             const float* __restrict__ base_w, const float* __restrict__ post1_w)
{
    int idx = blockIdx.x * blockDim.x + threadIdx.x;
    if (idx < 20*512*3072) {
        int l = idx / (512*3072); int r = idx % (512*3072);
        int m = r / 3072;         int kp = r % 3072;
        int sel = kp >> 10;       int k = kp & 1023;
        int blk = m >> 4;         int rr = m & 15;
        int d = blk*8 + (rr & 7); int gte = rr >> 3;
        const float* ws = gte ? gate_w : sig_w;
        const float* wp = gte ? pgate_w : psig_w;
        float v;
        if (k < 384)       v = ws[((size_t)(l*256 + d)*384 + k)*2 + 0];
        else if (k < 768)  v = ws[((size_t)(l*256 + d)*384 + (k-384))*2 + 1];
        else               v = wp[(size_t)(l*256 + d)*256 + (k-768)];
        bf16 h, lo; bsplit(v, h, lo);
        g_Wcat[idx] = (sel == 1) ? lo : h;
    }
    if (idx < 20*640*768) {
        int l = idx / (640*768); int r = idx % (640*768);
        int m = r / 768;         int kp = r % 768;
        int sel = kp >> 8;       int k = kp & 255;
        float v = (m < 256) ? skp_w[(size_t)(l*256 + m)*256 + k]
                            : res_w[(size_t)(l*384 + (m-256))*256 + k];
        bf16 h, lo; bsplit(v, h, lo);
        g_WB[idx] = (sel == 1) ? lo : h;
    }
    if (idx < 384*768) {
        int m = idx / 768; int kp = idx % 768;
        int sel = kp >> 8; int k = kp & 255;
        bf16 h, lo; bsplit(base_w[m*256 + k], h, lo);
        g_WbA[idx] = (sel == 1) ? lo : h;
    }
    if (idx < 512*768) {
        int m = idx / 768; int kp = idx % 768;
        int sel = kp >> 8; int k = kp & 255;
        bf16 h, lo; bsplit(post1_w[m*256 + k], h, lo);
        g_Wp1[idx] = (sel == 1) ? lo : h;
    }
    if (idx < 20*512) {
        int l = idx / 512; int m = idx % 512;
        int blk = m >> 4;  int rr = m & 15;
        int d = blk*8 + (rr & 7); int gte = rr >> 3;
        g_fb[idx] = gte ? gate_b[l*256 + d] : sig_b[l*256 + d];
    }
}

// ---------------- split / shift kernels ---------------------------------------
__global__ void split_plane(const float* __restrict__ src, bf16* __restrict__ h,
                            bf16* __restrict__ l, int R, int Tin, int TPout, int do_relu)
{
    int i = blockIdx.x * blockDim.x + threadIdx.x;
    if (i < R * Tin) {
        int t = i % Tin; int rr = i / Tin;
        float v = src[i];
        if (do_relu) v = fmaxf(v, 0.f);
        bf16 hh, ll; bsplit(v, hh, ll);
        size_t o = (size_t)rr * TPout + t;
        h[o] = hh; l[o] = ll;
    }
}
__global__ void split_cond(const float* __restrict__ src, bf16* __restrict__ h,
                           bf16* __restrict__ l)
{
    int i = blockIdx.x * blockDim.x + threadIdx.x;
    const int n = 4*128*TFULL;
    if (i < n) {
        int t = i % TFULL; int rc = i / TFULL;
        int c = rc & 127;  int b = rc >> 7;
        bf16 hh, ll; bsplit(src[i], hh, ll);
        size_t o = ((size_t)(b*256) + c)*TP + t;
        h[o] = hh; l[o] = ll;
    }
}
__global__ void shift1(const bf16* __restrict__ Xh, const bf16* __restrict__ Xl,
                       bf16* __restrict__ Sh, bf16* __restrict__ Sl)
{
    int i = blockIdx.x * blockDim.x + threadIdx.x;
    const int n = 4*384*TP;
    if (i < n) {
        int t = i % TP; size_t row = (size_t)(i / TP) * TP;
        bool ok = (t >= 1) && (t - 1 < TFULL);
        Sh[row + t] = ok ? Xh[row + t - 1] : __float2bfloat16(0.f);
        Sl[row + t] = ok ? Xl[row + t - 1] : __float2bfloat16(0.f);
    }
}

// ---------------- conditioning path (fp32, unchanged) -------------------------
__global__ void lc1_kernel(const float* __restrict__ lc_sparse, const int* __restrict__ jit,
                           const float* __restrict__ w, const float* __restrict__ bias)
{
    int o = blockIdx.x, b = blockIdx.y;
    int tx = threadIdx.x;
    __shared__ int   js[64];
    __shared__ float lcs[64][65];
    js[tx] = jit[b*64 + tx];
    __syncthreads();
    for (int s = 0; s < 64; s++)
        lcs[tx][s] = lc_sparse[(size_t)(b*64 + tx)*64 + js[s]];
    __syncthreads();
    if (tx < 62) {
        float acc = bias[o];
        for (int c = 0; c < 64; c++) {
            const float* wr = &w[(size_t)(o*64 + c)*3];
            acc += wr[0]*lcs[c][tx] + wr[1]*lcs[c][tx+1] + wr[2]*lcs[c][tx+2];
        }
        g_lc1[(size_t)(b*128 + o)*62 + tx] = acc;
    }
}

__global__ void tconv_kernel(const float* __restrict__ in, const float* __restrict__ w,
                             const float* __restrict__ bias, float* __restrict__ out,
                             int Lin, int Lout, int Kk, int S,
                             int inCh, int inB, int outCh, int outB)
{
    int t = blockIdx.x * blockDim.x + threadIdx.x;
    int o = blockIdx.y, b = blockIdx.z;
    if (t >= Lout) return;
    int r = (S - 1 - t) % S; if (r < 0) r += S;
    int u0 = (t + r - S + 1) / S;
    int jmax = (Kk - r + S - 1) / S;
    int jlim = Lin - u0; if (jlim < jmax) jmax = jlim;
    float acc = bias[o];
    for (int a = 0; a < 128; a++) {
        const float* inr = in + (size_t)b*inB + (size_t)a*inCh + u0;
        const float* wr  = w + (size_t)(a*128 + o)*Kk + (Kk - 1 - r);
        for (int j = 0; j < jmax; j++)
            acc += inr[j] * wr[-j*S];
    }
    out[(size_t)b*outB + (size_t)o*outCh + t] = acc;
}

__global__ void gc_kernel(const float* __restrict__ emb_w, const float* __restrict__ emb_b,
                          const int* __restrict__ spk,
                          bf16* __restrict__ ch, bf16* __restrict__ clo)
{
    int t = blockIdx.x * blockDim.x + threadIdx.x;
    int c = blockIdx.y, b = blockIdx.z;
    if (t < TFULL) {
        float v = emb_w[c*40 + spk[b]] + emb_b[c];
        bf16 h, l; bsplit(v, h, l);
        size_t o = ((size_t)(b*256) + 128 + c)*TP + t;
        ch[o] = h; clo[o] = l;
    }
}

// ---------------- bf16 3-term GEMM: BK=64, swizzled smem, dyn smem ------------
// grid = (M/128, columnTiles, batch) — x fastest => m-blocks of the same
// B-panel run adjacent => L2 reuse.
// smem: As stage s at sm[s*8192]:        idx = m*64  + (c^(m&7))*8 + w   (c=0..7)
//       Bs stage s at sm[16384+s*8192]:  idx = k*128 + ((c&8)|((c&7)^(k&7)))*8 + w  (c=0..15)
template<int MODE>
__global__ __launch_bounds__(256, 2) void gemm_tc(
    const bf16* __restrict__ W,
    const bf16* __restrict__ S0h, const bf16* __restrict__ S0l,
    const bf16* __restrict__ Sdh, const bf16* __restrict__ Sdl,
    const bf16* __restrict__ S1h, const bf16* __restrict__ S1l,
    const float* __restrict__ bias,
    bf16* __restrict__ O0b, bf16* __restrict__ O1b,
    float* __restrict__ O0f,
    const bf16* __restrict__ X2h, const bf16* __restrict__ X2l,
    float* __restrict__ skipbuf,
    int tStart, int tLen, int first, int tMin)
{
    constexpr int KB = (MODE == 1) ? 1024 : 256;
    constexpr int K  = 3 * KB;
    constexpr int BM = 128, BN = 128, BK = 64;
    constexpr int nK = K / BK;
    constexpr int SIN = (MODE == 3) ? OUTTP : TP;
    extern __shared__ __align__(16) bf16 sm[];

    const int tid  = threadIdx.x;
    const int lane = tid & 31, warp = tid >> 5;
    const int g    = lane >> 2, tig = lane & 3;
    const int wm0  = (warp >> 2) * 64, wn0 = (warp & 3) * 32;
    const int m0 = blockIdx.x * BM, bx = blockIdx.y, bb = blockIdx.z;
    const int tBase = tStart + bx * BN;
    const int cbase = bx * BN;
    const int l15 = lane & 15, lq = lane >> 4;

    const int ar = tid >> 1, c0 = (tid & 1) * 4;   // A loader: row ar, chunks c0..c0+3
    const int bk0 = tid >> 4, bcc = tid & 15;      // B loader: rows bk0+16j, chunk bcc

    auto rowptr = [&](int k) -> const bf16* {
        bool lo = (k >= 2*KB);
        int kk = (k >= 2*KB) ? (k - 2*KB) : ((k >= KB) ? (k - KB) : k);
        if (MODE == 1) {
            if (kk < 384) {
                const bf16* Xs = lo ? Sdl : Sdh;
                return Xs + ((size_t)(bb*384 + kk))*TP + tBase;
            } else if (kk < 768) {
                const bf16* Xs = lo ? S0l : S0h;
                return Xs + ((size_t)(bb*384 + (kk-384)))*TP + tBase;
            } else {
                const bf16* Cs = lo ? S1l : S1h;
                return Cs + ((size_t)(bb*256 + (kk-768)))*TP + tBase;
            }
        } else {
            const bf16* Ss = lo ? S0l : S0h;
            return Ss + ((size_t)(bb*256 + kk))*SIN + tBase;
        }
    };
    auto cpB = [&](uint32_t dst, const bf16* p) {
        uintptr_t a = (uintptr_t)p;
        if ((a & 15) == 0) {
            CP16(dst, p);
        } else if ((a & 7) == 0) {
            CP8(dst, p); CP8(dst + 8, p + 4);
        } else {
            CP4(dst, p); CP4(dst + 4, p + 2); CP4(dst + 8, p + 4); CP4(dst + 12, p + 6);
        }
    };
    auto issueStage = [&](int kt, int s) {
        const bf16* asrc = W + (size_t)(m0 + ar) * K + kt * BK + c0 * 8;
        #pragma unroll
        for (int i = 0; i < 4; i++) {
            int c = c0 + i;
            uint32_t ad = sptr(&sm[s*8192 + ar*64 + ((c ^ (ar & 7)) << 3)]);
            CP16(ad, asrc + i*8);
        }
        #pragma unroll
        for (int j = 0; j < 4; j++) {
            int k = bk0 + j*16;
            int phys = (bcc & 8) | ((bcc & 7) ^ (k & 7));
            uint32_t bd = sptr(&sm[16384 + s*8192 + k*128 + (phys << 3)]);
            cpB(bd, rowptr(kt*BK + k) + bcc*8);
        }
    };

    float acc[4][4][4];
    #pragma unroll
    for (int mi = 0; mi < 4; mi++)
        #pragma unroll
        for (int ni = 0; ni < 4; ni++)
            #pragma unroll
            for (int e = 0; e < 4; e++) acc[mi][ni][e] = 0.f;

    issueStage(0, 0);
    CP_COMMIT();

    int buf = 0;
    for (int kt = 0; kt < nK; kt++) {
        if (kt + 1 < nK) {
            issueStage(kt + 1, buf ^ 1);
            CP_COMMIT();
            asm volatile("cp.async.wait_group 1;\n");
        } else {
            asm volatile("cp.async.wait_group 0;\n");
        }
        __syncthreads();

        #pragma unroll
        for (int kk = 0; kk < BK; kk += 16) {
            uint32_t a[4][4], b[4][2];
            int ca = (kk >> 3) + lq;                       // A logical chunk 0..7
            #pragma unroll
            for (int mi = 0; mi < 4; mi++) {
                int row = wm0 + mi*16 + l15;
                uint32_t ad = sptr(&sm[buf*8192 + row*64 + ((ca ^ (row & 7)) << 3)]);
                LDSM_X4(a[mi][0], a[mi][1], a[mi][2], a[mi][3], ad);
            }
            #pragma unroll
            for (int n2 = 0; n2 < 2; n2++) {
                int k = kk + l15;
                int cb = ((wn0 + n2*16) >> 3) + lq;        // B logical chunk 0..15
                int phys = (cb & 8) | ((cb & 7) ^ (k & 7));
                uint32_t bd = sptr(&sm[16384 + buf*8192 + k*128 + (phys << 3)]);
                LDSM_X4T(b[n2*2][0], b[n2*2][1], b[n2*2+1][0], b[n2*2+1][1], bd);
            }
            #pragma unroll
            for (int mi = 0; mi < 4; mi++)
                #pragma unroll
                for (int ni = 0; ni < 4; ni++)
                    mma_bf16(acc[mi][ni], a[mi], b[ni]);
        }
        __syncthreads();
        buf ^= 1;
    }

    // ---------------- epilogues (global-column guards; packed bf16x2) ---------
    if (MODE == 1) {
        #pragma unroll
        for (int mi = 0; mi < 4; mi++) {
            int mblk = ((m0 + wm0) >> 4) + mi;
            int d = mblk*8 + g;
            float bfv = bias[mblk*16 + g];
            float bgv = bias[mblk*16 + 8 + g];
            size_t zoff = ((size_t)(bb*256 + d))*TP + tBase;
            #pragma unroll
            for (int ni = 0; ni < 4; ni++) {
                int col = wn0 + ni*8 + 2*tig;
                if (cbase + col < tLen) {   // tLen even => col valid implies col+1 valid
                    float f0 = acc[mi][ni][0] + bfv, g0 = acc[mi][ni][2] + bgv;
                    float f1 = acc[mi][ni][1] + bfv, g1 = acc[mi][ni][3] + bgv;
                    float z0 = acc_tanh(f0) * fast_sig(g0);
                    float z1 = acc_tanh(f1) * fast_sig(g1);
                    bf16 h0, l0, h1, l1; bsplit(z0, h0, l0); bsplit(z1, h1, l1);
                    *reinterpret_cast<uint32_t*>(&O0b[zoff + col]) = bpack(h0, h1);
                    *reinterpret_cast<uint32_t*>(&O1b[zoff + col]) = bpack(l0, l1);
                }
            }
        }
    } else if (MODE == 2) {
        #pragma unroll
        for (int mi = 0; mi < 4; mi++) {
            #pragma unroll
            for (int half = 0; half < 2; half++) {
                int m = m0 + wm0 + mi*16 + g + half*8;
                if (m < 256) {
                    float* srow = skipbuf + ((size_t)(bb*256 + m))*OUTTP;
                    #pragma unroll
                    for (int ni = 0; ni < 4; ni++) {
                        int col = wn0 + ni*8 + 2*tig;
                        #pragma unroll
                        for (int e = 0; e < 2; e++) {
                            int t = tBase + col + e;
                            if (cbase + col + e < tLen && t >= tMin) {
                                int ts = t - 2046;
                                if (ts >= 0) {
                                    float v = acc[mi][ni][half*2 + e];
                                    if (first) srow[ts] = v;
                                    else       srow[ts] += v;
                                }
                            }
                        }
                    }
                } else {
                    size_t off = ((size_t)(bb*384 + (m - 256)))*TP + tBase;
                    #pragma unroll
                    for (int ni = 0; ni < 4; ni++) {
                        int col = wn0 + ni*8 + 2*tig;
                        int t = tBase + col;
                        bool ok0 = (cbase + col < tLen) && (t >= tMin);
                        bool ok1 = (cbase + col < tLen) && (t + 1 >= tMin);
                        if (ok0 && ok1) {
                            float x0 = __bfloat162float(X2h[off+col])   + __bfloat162float(X2l[off+col]);
                            float x1 = __bfloat162float(X2h[off+col+1]) + __bfloat162float(X2l[off+col+1]);
                            float v0 = acc[mi][ni][half*2 + 0] + x0;
                            float v1 = acc[mi][ni][half*2 + 1] + x1;
                            bf16 h0, l0, h1, l1; bsplit(v0, h0, l0); bsplit(v1, h1, l1);
                            *reinterpret_cast<uint32_t*>(&O0b[off + col]) = bpack(h0, h1);
                            *reinterpret_cast<uint32_t*>(&O1b[off + col]) = bpack(l0, l1);
                        } else {
                            #pragma unroll
                            for (int e = 0; e < 2; e++) {
                                bool ok = (cbase + col + e < tLen) && (tBase + col + e >= tMin);
                                if (ok) {
                                    float xo = __bfloat162float(X2h[off+col+e])
                                             + __bfloat162float(X2l[off+col+e]);
                                    float v = acc[mi][ni][half*2 + e] + xo;
                                    bf16 vh, vl; bsplit(v, vh, vl);
                                    O0b[off + col + e] = vh;
                                    O1b[off + col + e] = vl;
                                }
                            }
                        }
                    }
                }
            }
        }
    } else {  // MODE 0 (split bf16 out) / MODE 3 (fp32 relu out)
        #pragma unroll
        for (int mi = 0; mi < 4; mi++) {
            #pragma unroll
            for (int half = 0; half < 2; half++) {
                int m = m0 + wm0 + mi*16 + g + half*8;
                float bv = bias[m];
                size_t off;
                if (MODE == 0) off = ((size_t)(bb*384 + m))*TP + tBase;
                else           off = ((size_t)(bb*512 + m))*OUTTP + tBase;
                #pragma unroll
                for (int ni = 0; ni < 4; ni++) {
                    int col = wn0 + ni*8 + 2*tig;
                    if (cbase + col < tLen) {   // even tLen => pair valid
                        float v0 = acc[mi][ni][half*2 + 0] + bv;
                        float v1 = acc[mi][ni][half*2 + 1] + bv;
                        if (MODE == 3) {
                            O0f[off + col]     = fmaxf(v0, 0.f);
                            O0f[off + col + 1] = fmaxf(v1, 0.f);
                        } else {
                            bf16 h0, l0, h1, l1; bsplit(v0, h0, l0); bsplit(v1, h1, l1);
                            *reinterpret_cast<uint32_t*>(&O0b[off + col]) = bpack(h0, h1);
                            *reinterpret_cast<uint32_t*>(&O1b[off + col]) = bpack(l0, l1);
                        }
                    }
                }
            }
        }
    }
}

// ---------------- post2 + log_softmax ----------------------------------------
__global__ __launch_bounds__(256) void post2_softmax(const float* __restrict__ H,
                                                     const float* __restrict__ W2,
                                                     const float* __restrict__ B2,
                                                     float* __restrict__ out)
{
    int b = blockIdx.y;
    int t0 = blockIdx.x * 16;
    int q = threadIdx.x;
    __shared__ float Hs[512*16];
    __shared__ float Ws[256*16];

    for (int idx = q; idx < 512*16; idx += 256) {
        int p = idx >> 4, j = idx & 15;
        int t = t0 + j;
        Hs[idx] = (t < OUTT) ? H[((size_t)(b*512 + p))*OUTTP + t] : 0.f;
    }
    float acc[16];
    float bq = B2[q];
    #pragma unroll
    for (int j = 0; j < 16; j++) acc[j] = bq;

    for (int p0 = 0; p0 < 512; p0 += 16) {
        __syncthreads();
        for (int idx = q; idx < 256*16; idx += 256) {
            int qq = idx >> 4, pp = idx & 15;
            Ws[idx] = W2[(size_t)qq*512 + p0 + pp];
        }
        __syncthreads();
        #pragma unroll
        for (int pp = 0; pp < 16; pp++) {
            float w = Ws[q*16 + pp];
            const float* hp = &Hs[(p0 + pp)*16];
            #pragma unroll
            for (int j = 0; j < 16; j++) acc[j] += w * hp[j];
        }
    }
    __syncthreads();
    #pragma unroll
    for (int j = 0; j < 16; j++) Hs[q*16 + j] = acc[j];
    __syncthreads();
    if (q < 16) {
        float mx = -1e30f;
        for (int qq = 0; qq < 256; qq++) mx = fmaxf(mx, Hs[qq*16 + q]);
        float s = 0.f;
        for (int qq = 0; qq < 256; qq++) s += expf(Hs[qq*16 + q] - mx);
        Ws[q] = mx + logf(s);
    }
    __syncthreads();
    #pragma unroll
    for (int j = 0; j < 16; j++) {
        int t = t0 + j;
        if (t < OUTT) out[((size_t)(b*256 + q))*OUTT + t] = acc[j] - Ws[j];
    }
}

// ---------------- host --------------------------------------------------------
static const int h_dils[20] = {1,2,4,8,16,32,64,128,256,512,1,2,4,8,16,32,64,128,256,512};
#define GEMM_SMEM 65536

extern "C" void kernel_launch(void* const* d_in, const int* in_sizes, int n_in,
                              void* d_out, int out_size)
{
    (void)in_sizes; (void)n_in; (void)out_size;
    const float* wav       = (const float*)d_in[0];
    const float* lc_sparse = (const float*)d_in[1];
    const float* lc_conv_w = (const float*)d_in[2];
    const float* lc_conv_b = (const float*)d_in[3];
    const float* ups_w0    = (const float*)d_in[4];
    const float* ups_b0    = (const float*)d_in[5];
    const float* ups_w1    = (const float*)d_in[6];
    const float* ups_b1    = (const float*)d_in[7];
    const float* ups_w2    = (const float*)d_in[8];
    const float* ups_b2    = (const float*)d_in[9];
    const float* ups_w3    = (const float*)d_in[10];
    const float* ups_b3    = (const float*)d_in[11];
    const float* emb_w     = (const float*)d_in[12];
    const float* emb_b     = (const float*)d_in[13];
    const float* base_w    = (const float*)d_in[14];
    const float* base_b    = (const float*)d_in[15];
    const float* sig_w     = (const float*)d_in[16];
    const float* sig_b     = (const float*)d_in[17];
    const float* gate_w    = (const float*)d_in[18];
    const float* gate_b    = (const float*)d_in[19];
    const float* psig_w    = (const float*)d_in[20];
    const float* pgate_w   = (const float*)d_in[21];
    const float* skp_w     = (const float*)d_in[22];
    const float* res_w     = (const float*)d_in[23];
    const float* post1_w   = (const float*)d_in[24];
    const float* post1_b   = (const float*)d_in[25];
    const float* post2_w   = (const float*)d_in[26];
    const float* post2_b   = (const float*)d_in[27];
    const int*   spk       = (const int*)d_in[28];
    const int*   jit       = (const int*)d_in[29];
    float* out = (float*)d_out;

    bf16 *pXh0r,*pXl0r,*pXh1r,*pXl1r,*pXshr,*pXslr,*pCh,*pCl,*pZh,*pZl,*pWh,*pWl,*pSkh,*pSkl;
    bf16 *pWcat,*pWB,*pWbA,*pWp1;
    float *pCF,*pSkip,*pH,*pfb,*pLc1,*pUpA,*pUpB;
    cudaGetSymbolAddress((void**)&pXh0r, g_Xh0);
    cudaGetSymbolAddress((void**)&pXl0r, g_Xl0);
    cudaGetSymbolAddress((void**)&pXh1r, g_Xh1);
    cudaGetSymbolAddress((void**)&pXl1r, g_Xl1);
    cudaGetSymbolAddress((void**)&pXshr, g_Xsh);
    cudaGetSymbolAddress((void**)&pXslr, g_Xsl);
    cudaGetSymbolAddress((void**)&pCh,   g_condh);
    cudaGetSymbolAddress((void**)&pCl,   g_condl);
    cudaGetSymbolAddress((void**)&pCF,   g_condF);
    cudaGetSymbolAddress((void**)&pZh,   g_Zh);
    cudaGetSymbolAddress((void**)&pZl,   g_Zl);
    cudaGetSymbolAddress((void**)&pWh,   g_wavh);
    cudaGetSymbolAddress((void**)&pWl,   g_wavl);
    cudaGetSymbolAddress((void**)&pSkip, g_skip);
    cudaGetSymbolAddress((void**)&pSkh,  g_skh);
    cudaGetSymbolAddress((void**)&pSkl,  g_skl);
    cudaGetSymbolAddress((void**)&pH,    g_H);
    cudaGetSymbolAddress((void**)&pWcat, g_Wcat);
    cudaGetSymbolAddress((void**)&pWB,   g_WB);
    cudaGetSymbolAddress((void**)&pWbA,  g_WbA);
    cudaGetSymbolAddress((void**)&pWp1,  g_Wp1);
    cudaGetSymbolAddress((void**)&pfb,   g_fb);
    cudaGetSymbolAddress((void**)&pLc1,  g_lc1);
    cudaGetSymbolAddress((void**)&pUpA,  g_upA);
    cudaGetSymbolAddress((void**)&pUpB,  g_upB);
    bf16* pXh0 = pXh0r + LEAD;  bf16* pXl0 = pXl0r + LEAD;
    bf16* pXh1 = pXh1r + LEAD;  bf16* pXl1 = pXl1r + LEAD;
    bf16* pXsh = pXshr + LEAD;  bf16* pXsl = pXslr + LEAD;

    cudaFuncSetAttribute(gemm_tc<0>, cudaFuncAttributeMaxDynamicSharedMemorySize, GEMM_SMEM);
    cudaFuncSetAttribute(gemm_tc<1>, cudaFuncAttributeMaxDynamicSharedMemorySize, GEMM_SMEM);
    cudaFuncSetAttribute(gemm_tc<2>, cudaFuncAttributeMaxDynamicSharedMemorySize, GEMM_SMEM);
    cudaFuncSetAttribute(gemm_tc<3>, cudaFuncAttributeMaxDynamicSharedMemorySize, GEMM_SMEM);

    {
        int n = 20*512*3072;
        pack_weights<<<(n + 255)/256, 256>>>(sig_w, sig_b, gate_w, gate_b,
                                             psig_w, pgate_w, skp_w, res_w,
                                             base_w, post1_w);
    }
    {
        int n = 4*256*TFULL;
        split_plane<<<(n + 255)/256, 256>>>(wav, pWh, pWl, 4*256, TFULL, TP, 0);
    }

    // conditioning path
    lc1_kernel<<<dim3(128, 4), 64>>>(lc_sparse, jit, lc_conv_w, lc_conv_b);
    tconv_kernel<<<dim3((290+127)/128, 128, 4), 128>>>(pLc1, ups_w0, ups_b0, pUpA,
        62, 290, 25, 5, 62, 128*62, 290, 128*290);
    tconv_kernel<<<dim3((1148+127)/128, 128, 4), 128>>>(pUpA, ups_w1, ups_b1, pUpB,
        290, 1148, 16, 4, 290, 128*290, 1148, 128*1148);
    tconv_kernel<<<dim3((4580+127)/128, 128, 4), 128>>>(pUpB, ups_w2, ups_b2, pUpA,
        1148, 4580, 16, 4, 1148, 128*1148, 4580, 128*4580);
    tconv_kernel<<<dim3((TFULL+127)/128, 128, 4), 128>>>(pUpA, ups_w3, ups_b3, pCF,
        4580, TFULL, 16, 4, 4580, 128*4580, TFULL, 128*TFULL);
    {
        int n = 4*128*TFULL;
        split_cond<<<(n + 255)/256, 256>>>(pCF, pCh, pCl);
    }
    gc_kernel<<<dim3((TFULL+255)/256, 128, 4), 256>>>(emb_w, emb_b, spk, pCh, pCl);

    // base 1x1 conv -> X0 planes
    gemm_tc<0><<<dim3(3, (TFULL+127)/128, 4), 256, GEMM_SMEM>>>(pWbA, pWh, pWl,
        nullptr, nullptr, nullptr, nullptr, base_b,
        pXh0, pXl0, nullptr, nullptr, nullptr, nullptr, 0, TFULL, 0, 0);

    // 20 residual layers
    int cum = 0;
    for (int i = 0; i < 20; i++) {
        int dil = h_dils[i];
        int cl = cum + dil;
        int tA = cl & ~7;
        int tLen = TFULL - tA;
        bf16* Xih = (i % 2 == 0) ? pXh0 : pXh1;  bf16* Xil = (i % 2 == 0) ? pXl0 : pXl1;
        bf16* Xoh = (i % 2 == 0) ? pXh1 : pXh0;  bf16* Xol = (i % 2 == 0) ? pXl1 : pXl0;
        const bf16 *Xdh, *Xdl;
        if (dil == 1) {
            int n = 4*384*TP;
            shift1<<<(n + 255)/256, 256>>>(Xih, Xil, pXsh, pXsl);
            Xdh = pXsh; Xdl = pXsl;
        } else {
            Xdh = Xih - dil; Xdl = Xil - dil;
        }
        int gx = (tLen + 127)/128;
        gemm_tc<1><<<dim3(4, gx, 4), 256, GEMM_SMEM>>>(pWcat + (size_t)i*512*3072,
            Xih, Xil, Xdh, Xdl, pCh, pCl, pfb + i*512,
            pZh, pZl, nullptr, nullptr, nullptr, nullptr, tA, tLen, 0, cl);
        gemm_tc<2><<<dim3(5, gx, 4), 256, GEMM_SMEM>>>(pWB + (size_t)i*640*768,
            pZh, pZl, nullptr, nullptr, nullptr, nullptr, nullptr,
            Xoh, Xol, nullptr, Xih, Xil, pSkip, tA, tLen, (i == 0) ? 1 : 0, cl);
        cum = cl;
    }

    {
        int n = 4*256*OUTTP;
        split_plane<<<(n + 255)/256, 256>>>(pSkip, pSkh, pSkl, 4*256, OUTTP, OUTTP, 1);
    }
    gemm_tc<3><<<dim3(4, (OUTT+127)/128, 4), 256, GEMM_SMEM>>>(pWp1, pSkh, pSkl,
        nullptr, nullptr, nullptr, nullptr, post1_b,
        nullptr, nullptr, pH, nullptr, nullptr, nullptr, 0, OUTT, 0, 0);
    post2_softmax<<<dim3((OUTT+15)/16, 4), 256>>>(pH, post2_w, post2_b, out);
}

// round 14
// speedup vs baseline: 2.1742x; 1.0161x over previous
#include <cuda_runtime.h>
#include <cuda_bf16.h>
#include <cstdint>
#include <math.h>

// ----------------------------------------------------------------------------
// WaveNet on GB300/B200 — round 13: resubmit of R12 (infra-only failure;
// content frozen until a measurement exists).
// 3-stage cp.async pipeline (1 sync/iter), ncu -s 5 lands on gemm_tc<0>.
// bf16 3-term mma.sync GEMMs, BK=64, XOR-swizzled conflict-free smem,
// L2-reuse grid order, packed bf16x2 epilogue.
//   A·B ≈ Ah·Bh + Al·Bh + Ah·Bl ; A' = [Wh|Wl|Wh] bf16, B' = [Bh;Bh;Bl] bf16.
//   B=4, T=18308, 20 layers, dils [1..512]x2, TOTAL_LW=2046, OUTT=16262
// ----------------------------------------------------------------------------

#define TFULL 18308
#define TP    18312      // padded bf16 plane row stride (mult of 8)
#define OUTT  16262
#define OUTTP 16264
#define SLACK 4096
#define LEAD  64

#define XPE   (4u*384u*18312u)
#define CPE   (4u*256u*18312u)
#define SPE   (4u*256u*16264u)

typedef __nv_bfloat16 bf16;

// ---------------- scratch (device globals: allocation-free, zero-init) ------
__device__ __align__(128) bf16  g_Xh0[XPE + SLACK + LEAD];
__device__ __align__(128) bf16  g_Xl0[XPE + SLACK + LEAD];
__device__ __align__(128) bf16  g_Xh1[XPE + SLACK + LEAD];
__device__ __align__(128) bf16  g_Xl1[XPE + SLACK + LEAD];
__device__ __align__(128) bf16  g_Xsh[XPE + SLACK + LEAD];   // X shifted by 1 (dil=1)
__device__ __align__(128) bf16  g_Xsl[XPE + SLACK + LEAD];
__device__ __align__(128) bf16  g_condh[CPE + SLACK];
__device__ __align__(128) bf16  g_condl[CPE + SLACK];
__device__ __align__(128) float g_condF[4u*128u*18308u];
__device__ __align__(128) bf16  g_Zh[CPE + SLACK];
__device__ __align__(128) bf16  g_Zl[CPE + SLACK];
__device__ __align__(128) bf16  g_wavh[CPE + SLACK];
__device__ __align__(128) bf16  g_wavl[CPE + SLACK];
__device__ __align__(128) float g_skip[SPE + SLACK];
__device__ __align__(128) bf16  g_skh[SPE + SLACK];
__device__ __align__(128) bf16  g_skl[SPE + SLACK];
__device__ __align__(128) float g_H[4u*512u*16264u + SLACK];
__device__ __align__(128) bf16  g_Wcat[20u*512u*3072u];
__device__ __align__(128) bf16  g_WB[20u*640u*768u];
__device__ __align__(128) bf16  g_WbA[384u*768u];
__device__ __align__(128) bf16  g_Wp1[512u*768u];
__device__ __align__(128) float g_fb[20u*512u];
__device__ __align__(128) float g_lc1[4u*128u*62u];
__device__ __align__(128) float g_upA[4u*128u*4580u];
__device__ __align__(128) float g_upB[4u*128u*4580u];

// ---------------- helpers -----------------------------------------------------
__device__ __forceinline__ uint32_t sptr(const void* p) {
    return (uint32_t)__cvta_generic_to_shared(p);
}
#define CP16(dst, src) \
    asm volatile("cp.async.cg.shared.global [%0], [%1], 16;\n" :: "r"(dst), "l"(src))
#define CP8(dst, src) \
    asm volatile("cp.async.ca.shared.global [%0], [%1], 8;\n" :: "r"(dst), "l"(src))
#define CP4(dst, src) \
    asm volatile("cp.async.ca.shared.global [%0], [%1], 4;\n" :: "r"(dst), "l"(src))
#define CP_COMMIT() asm volatile("cp.async.commit_group;\n")

__device__ __forceinline__ void mma_bf16(float c[4], const uint32_t a[4], const uint32_t b[2]) {
    asm volatile(
        "mma.sync.aligned.m16n8k16.row.col.f32.bf16.bf16.f32 "
        "{%0,%1,%2,%3}, {%4,%5,%6,%7}, {%8,%9}, {%0,%1,%2,%3};"
        : "+f"(c[0]), "+f"(c[1]), "+f"(c[2]), "+f"(c[3])
        : "r"(a[0]), "r"(a[1]), "r"(a[2]), "r"(a[3]), "r"(b[0]), "r"(b[1]));
}
#define LDSM_X4(r0,r1,r2,r3,addr) \
    asm volatile("ldmatrix.sync.aligned.m8n8.x4.shared.b16 {%0,%1,%2,%3}, [%4];" \
        : "=r"(r0), "=r"(r1), "=r"(r2), "=r"(r3) : "r"(addr))
#define LDSM_X4T(r0,r1,r2,r3,addr) \
    asm volatile("ldmatrix.sync.aligned.m8n8.x4.trans.shared.b16 {%0,%1,%2,%3}, [%4];" \
        : "=r"(r0), "=r"(r1), "=r"(r2), "=r"(r3) : "r"(addr))

__device__ __forceinline__ float fast_sig(float x) {
    float e; asm("ex2.approx.f32 %0, %1;" : "=f"(e) : "f"(-x * 1.4426950408889634f));
    float r; asm("rcp.approx.f32 %0, %1;" : "=f"(r) : "f"(1.f + e));
    return r;
}
__device__ __forceinline__ float acc_tanh(float x) { return 2.f * fast_sig(2.f * x) - 1.f; }
__device__ __forceinline__ void bsplit(float v, bf16& h, bf16& l) {
    h = __float2bfloat16(v);
    l = __float2bfloat16(v - __bfloat162float(h));
}
__device__ __forceinline__ uint32_t bpack(bf16 a, bf16 b) {
    uint16_t ua = __bfloat16_as_ushort(a), ub = __bfloat16_as_ushort(b);
    return (uint32_t)ua | ((uint32_t)ub << 16);
}

// ---------------- weight packing (hi|lo|hi augmented, bf16) -------------------
__global__ void pack_weights(const float* __restrict__ sig_w, const float* __restrict__ sig_b,
                             const float* __restrict__ gate_w, const float* __restrict__ gate_b,
                             const float* __restrict__ psig_w, const float* __restrict__ pgate_w,
                             const float* __restrict__ skp_w, const float* __restrict__ res_w,
                             const float* __restrict__ base_w, const float* __restrict__ post1_w)
{
    int idx = blockIdx.x * blockDim.x + threadIdx.x;
    if (idx < 20*512*3072) {
        int l = idx / (512*3072); int r = idx % (512*3072);
        int m = r / 3072;         int kp = r % 3072;
        int sel = kp >> 10;       int k = kp & 1023;
        int blk = m >> 4;         int rr = m & 15;
        int d = blk*8 + (rr & 7); int gte = rr >> 3;
        const float* ws = gte ? gate_w : sig_w;
        const float* wp = gte ? pgate_w : psig_w;
        float v;
        if (k < 384)       v = ws[((size_t)(l*256 + d)*384 + k)*2 + 0];
        else if (k < 768)  v = ws[((size_t)(l*256 + d)*384 + (k-384))*2 + 1];
        else               v = wp[(size_t)(l*256 + d)*256 + (k-768)];
        bf16 h, lo; bsplit(v, h, lo);
        g_Wcat[idx] = (sel == 1) ? lo : h;
    }
    if (idx < 20*640*768) {
        int l = idx / (640*768); int r = idx % (640*768);
        int m = r / 768;         int kp = r % 768;
        int sel = kp >> 8;       int k = kp & 255;
        float v = (m < 256) ? skp_w[(size_t)(l*256 + m)*256 + k]
                            : res_w[(size_t)(l*384 + (m-256))*256 + k];
        bf16 h, lo; bsplit(v, h, lo);
        g_WB[idx] = (sel == 1) ? lo : h;
    }
    if (idx < 384*768) {
        int m = idx / 768; int kp = idx % 768;
        int sel = kp >> 8; int k = kp & 255;
        bf16 h, lo; bsplit(base_w[m*256 + k], h, lo);
        g_WbA[idx] = (sel == 1) ? lo : h;
    }
    if (idx < 512*768) {
        int m = idx / 768; int kp = idx % 768;
        int sel = kp >> 8; int k = kp & 255;
        bf16 h, lo; bsplit(post1_w[m*256 + k], h, lo);
        g_Wp1[idx] = (sel == 1) ? lo : h;
    }
    if (idx < 20*512) {
        int l = idx / 512; int m = idx % 512;
        int blk = m >> 4;  int rr = m & 15;
        int d = blk*8 + (rr & 7); int gte = rr >> 3;
        g_fb[idx] = gte ? gate_b[l*256 + d] : sig_b[l*256 + d];
    }
}

// ---------------- split / shift kernels ---------------------------------------
__global__ void split_plane(const float* __restrict__ src, bf16* __restrict__ h,
                            bf16* __restrict__ l, int R, int Tin, int TPout, int do_relu)
{
    int i = blockIdx.x * blockDim.x + threadIdx.x;
    if (i < R * Tin) {
        int t = i % Tin; int rr = i / Tin;
        float v = src[i];
        if (do_relu) v = fmaxf(v, 0.f);
        bf16 hh, ll; bsplit(v, hh, ll);
        size_t o = (size_t)rr * TPout + t;
        h[o] = hh; l[o] = ll;
    }
}
__global__ void split_cond(const float* __restrict__ src, bf16* __restrict__ h,
                           bf16* __restrict__ l)
{
    int i = blockIdx.x * blockDim.x + threadIdx.x;
    const int n = 4*128*TFULL;
    if (i < n) {
        int t = i % TFULL; int rc = i / TFULL;
        int c = rc & 127;  int b = rc >> 7;
        bf16 hh, ll; bsplit(src[i], hh, ll);
        size_t o = ((size_t)(b*256) + c)*TP + t;
        h[o] = hh; l[o] = ll;
    }
}
__global__ void shift1(const bf16* __restrict__ Xh, const bf16* __restrict__ Xl,
                       bf16* __restrict__ Sh, bf16* __restrict__ Sl)
{
    int i = blockIdx.x * blockDim.x + threadIdx.x;
    const int n = 4*384*TP;
    if (i < n) {
        int t = i % TP; size_t row = (size_t)(i / TP) * TP;
        bool ok = (t >= 1) && (t - 1 < TFULL);
        Sh[row + t] = ok ? Xh[row + t - 1] : __float2bfloat16(0.f);
        Sl[row + t] = ok ? Xl[row + t - 1] : __float2bfloat16(0.f);
    }
}

// ---------------- conditioning path (fp32, unchanged) -------------------------
__global__ void lc1_kernel(const float* __restrict__ lc_sparse, const int* __restrict__ jit,
                           const float* __restrict__ w, const float* __restrict__ bias)
{
    int o = blockIdx.x, b = blockIdx.y;
    int tx = threadIdx.x;
    __shared__ int   js[64];
    __shared__ float lcs[64][65];
    js[tx] = jit[b*64 + tx];
    __syncthreads();
    for (int s = 0; s < 64; s++)
        lcs[tx][s] = lc_sparse[(size_t)(b*64 + tx)*64 + js[s]];
    __syncthreads();
    if (tx < 62) {
        float acc = bias[o];
        for (int c = 0; c < 64; c++) {
            const float* wr = &w[(size_t)(o*64 + c)*3];
            acc += wr[0]*lcs[c][tx] + wr[1]*lcs[c][tx+1] + wr[2]*lcs[c][tx+2];
        }
        g_lc1[(size_t)(b*128 + o)*62 + tx] = acc;
    }
}

__global__ void tconv_kernel(const float* __restrict__ in, const float* __restrict__ w,
                             const float* __restrict__ bias, float* __restrict__ out,
                             int Lin, int Lout, int Kk, int S,
                             int inCh, int inB, int outCh, int outB)
{
    int t = blockIdx.x * blockDim.x + threadIdx.x;
    int o = blockIdx.y, b = blockIdx.z;
    if (t >= Lout) return;
    int r = (S - 1 - t) % S; if (r < 0) r += S;
    int u0 = (t + r - S + 1) / S;
    int jmax = (Kk - r + S - 1) / S;
    int jlim = Lin - u0; if (jlim < jmax) jmax = jlim;
    float acc = bias[o];
    for (int a = 0; a < 128; a++) {
        const float* inr = in + (size_t)b*inB + (size_t)a*inCh + u0;
        const float* wr  = w + (size_t)(a*128 + o)*Kk + (Kk - 1 - r);
        for (int j = 0; j < jmax; j++)
            acc += inr[j] * wr[-j*S];
    }
    out[(size_t)b*outB + (size_t)o*outCh + t] = acc;
}

__global__ void gc_kernel(const float* __restrict__ emb_w, const float* __restrict__ emb_b,
                          const int* __restrict__ spk,
                          bf16* __restrict__ ch, bf16* __restrict__ clo)
{
    int t = blockIdx.x * blockDim.x + threadIdx.x;
    int c = blockIdx.y, b = blockIdx.z;
    if (t < TFULL) {
        float v = emb_w[c*40 + spk[b]] + emb_b[c];
        bf16 h, l; bsplit(v, h, l);
        size_t o = ((size_t)(b*256) + 128 + c)*TP + t;
        ch[o] = h; clo[o] = l;
    }
}

// ---------------- bf16 3-term GEMM: BK=64, 3-stage pipeline, 1 sync/iter ------
// grid = (M/128, columnTiles, batch) — x fastest => L2 reuse of B panels.
// smem (3 stages): A stage s at sm[s*8192]          (128 rows x 64, 128B rows)
//                  B stage s at sm[24576 + s*8192]  (64 rows x 128, 256B rows)
// swizzle: A chunk c -> c^(m&7);  B chunk c -> (c&8)|((c&7)^(k&7))
template<int MODE>
__global__ __launch_bounds__(256, 2) void gemm_tc(
    const bf16* __restrict__ W,
    const bf16* __restrict__ S0h, const bf16* __restrict__ S0l,
    const bf16* __restrict__ Sdh, const bf16* __restrict__ Sdl,
    const bf16* __restrict__ S1h, const bf16* __restrict__ S1l,
    const float* __restrict__ bias,
    bf16* __restrict__ O0b, bf16* __restrict__ O1b,
    float* __restrict__ O0f,
    const bf16* __restrict__ X2h, const bf16* __restrict__ X2l,
    float* __restrict__ skipbuf,
    int tStart, int tLen, int first, int tMin)
{
    constexpr int KB = (MODE == 1) ? 1024 : 256;
    constexpr int K  = 3 * KB;
    constexpr int BM = 128, BN = 128, BK = 64;
    constexpr int nK = K / BK;
    constexpr int SIN = (MODE == 3) ? OUTTP : TP;
    extern __shared__ __align__(16) bf16 sm[];

    const int tid  = threadIdx.x;
    const int lane = tid & 31, warp = tid >> 5;
    const int g    = lane >> 2, tig = lane & 3;
    const int wm0  = (warp >> 2) * 64, wn0 = (warp & 3) * 32;
    const int m0 = blockIdx.x * BM, bx = blockIdx.y, bb = blockIdx.z;
    const int tBase = tStart + bx * BN;
    const int cbase = bx * BN;
    const int l15 = lane & 15, lq = lane >> 4;

    const int ar = tid >> 1, c0 = (tid & 1) * 4;   // A loader: row ar, chunks c0..c0+3
    const int bk0 = tid >> 4, bcc = tid & 15;      // B loader: rows bk0+16j, chunk bcc

    auto rowptr = [&](int k) -> const bf16* {
        bool lo = (k >= 2*KB);
        int kk = (k >= 2*KB) ? (k - 2*KB) : ((k >= KB) ? (k - KB) : k);
        if (MODE == 1) {
            if (kk < 384) {
                const bf16* Xs = lo ? Sdl : Sdh;
                return Xs + ((size_t)(bb*384 + kk))*TP + tBase;
            } else if (kk < 768) {
                const bf16* Xs = lo ? S0l : S0h;
                return Xs + ((size_t)(bb*384 + (kk-384)))*TP + tBase;
            } else {
                const bf16* Cs = lo ? S1l : S1h;
                return Cs + ((size_t)(bb*256 + (kk-768)))*TP + tBase;
            }
        } else {
            const bf16* Ss = lo ? S0l : S0h;
            return Ss + ((size_t)(bb*256 + kk))*SIN + tBase;
        }
    };
    auto cpB = [&](uint32_t dst, const bf16* p) {
        uintptr_t a = (uintptr_t)p;
        if ((a & 15) == 0) {
            CP16(dst, p);
        } else if ((a & 7) == 0) {
            CP8(dst, p); CP8(dst + 8, p + 4);
        } else {
            CP4(dst, p); CP4(dst + 4, p + 2); CP4(dst + 8, p + 4); CP4(dst + 12, p + 6);
        }
    };
    auto issueStage = [&](int kt, int s) {
        const bf16* asrc = W + (size_t)(m0 + ar) * K + kt * BK + c0 * 8;
        #pragma unroll
        for (int i = 0; i < 4; i++) {
            int c = c0 + i;
            uint32_t ad = sptr(&sm[s*8192 + ar*64 + ((c ^ (ar & 7)) << 3)]);
            CP16(ad, asrc + i*8);
        }
        #pragma unroll
        for (int j = 0; j < 4; j++) {
            int k = bk0 + j*16;
            int phys = (bcc & 8) | ((bcc & 7) ^ (k & 7));
            uint32_t bd = sptr(&sm[24576 + s*8192 + k*128 + (phys << 3)]);
            cpB(bd, rowptr(kt*BK + k) + bcc*8);
        }
    };

    float acc[4][4][4];
    #pragma unroll
    for (int mi = 0; mi < 4; mi++)
        #pragma unroll
        for (int ni = 0; ni < 4; ni++)
            #pragma unroll
            for (int e = 0; e < 4; e++) acc[mi][ni][e] = 0.f;

    issueStage(0, 0); CP_COMMIT();
    issueStage(1, 1); CP_COMMIT();

    int sc = 0, si = 2;
    for (int kt = 0; kt < nK; kt++) {
        if (kt + 1 < nK) {
            asm volatile("cp.async.wait_group 1;\n");
        } else {
            asm volatile("cp.async.wait_group 0;\n");
        }
        __syncthreads();   // stage sc ready for all; stage si safe to overwrite

        if (kt + 2 < nK) {
            issueStage(kt + 2, si);
            CP_COMMIT();
            if (++si == 3) si = 0;
        }

        #pragma unroll
        for (int kk = 0; kk < BK; kk += 16) {
            uint32_t a[4][4], b[4][2];
            int ca = (kk >> 3) + lq;                       // A logical chunk 0..7
            #pragma unroll
            for (int mi = 0; mi < 4; mi++) {
                int row = wm0 + mi*16 + l15;
                uint32_t ad = sptr(&sm[sc*8192 + row*64 + ((ca ^ (row & 7)) << 3)]);
                LDSM_X4(a[mi][0], a[mi][1], a[mi][2], a[mi][3], ad);
            }
            #pragma unroll
            for (int n2 = 0; n2 < 2; n2++) {
                int k = kk + l15;
                int cb = ((wn0 + n2*16) >> 3) + lq;        // B logical chunk 0..15
                int phys = (cb & 8) | ((cb & 7) ^ (k & 7));
                uint32_t bd = sptr(&sm[24576 + sc*8192 + k*128 + (phys << 3)]);
                LDSM_X4T(b[n2*2][0], b[n2*2][1], b[n2*2+1][0], b[n2*2+1][1], bd);
            }
            #pragma unroll
            for (int mi = 0; mi < 4; mi++)
                #pragma unroll
                for (int ni = 0; ni < 4; ni++)
                    mma_bf16(acc[mi][ni], a[mi], b[ni]);
        }
        if (++sc == 3) sc = 0;
    }

    // ---------------- epilogues (global-column guards; packed bf16x2) ---------
    if (MODE == 1) {
        #pragma unroll
        for (int mi = 0; mi < 4; mi++) {
            int mblk = ((m0 + wm0) >> 4) + mi;
            int d = mblk*8 + g;
            float bfv = bias[mblk*16 + g];
            float bgv = bias[mblk*16 + 8 + g];
            size_t zoff = ((size_t)(bb*256 + d))*TP + tBase;
            #pragma unroll
            for (int ni = 0; ni < 4; ni++) {
                int col = wn0 + ni*8 + 2*tig;
                if (cbase + col < tLen) {   // tLen even => col valid implies col+1 valid
                    float f0 = acc[mi][ni][0] + bfv, g0 = acc[mi][ni][2] + bgv;
                    float f1 = acc[mi][ni][1] + bfv, g1 = acc[mi][ni][3] + bgv;
                    float z0 = acc_tanh(f0) * fast_sig(g0);
                    float z1 = acc_tanh(f1) * fast_sig(g1);
                    bf16 h0, l0, h1, l1; bsplit(z0, h0, l0); bsplit(z1, h1, l1);
                    *reinterpret_cast<uint32_t*>(&O0b[zoff + col]) = bpack(h0, h1);
                    *reinterpret_cast<uint32_t*>(&O1b[zoff + col]) = bpack(l0, l1);
                }
            }
        }
    } else if (MODE == 2) {
        #pragma unroll
        for (int mi = 0; mi < 4; mi++) {
            #pragma unroll
            for (int half = 0; half < 2; half++) {
                int m = m0 + wm0 + mi*16 + g + half*8;
                if (m < 256) {
                    float* srow = skipbuf + ((size_t)(bb*256 + m))*OUTTP;
                    #pragma unroll
                    for (int ni = 0; ni < 4; ni++) {
                        int col = wn0 + ni*8 + 2*tig;
                        #pragma unroll
                        for (int e = 0; e < 2; e++) {
                            int t = tBase + col + e;
                            if (cbase + col + e < tLen && t >= tMin) {
                                int ts = t - 2046;
                                if (ts >= 0) {
                                    float v = acc[mi][ni][half*2 + e];
                                    if (first) srow[ts] = v;
                                    else       srow[ts] += v;
                                }
                            }
                        }
                    }
                } else {
                    size_t off = ((size_t)(bb*384 + (m - 256)))*TP + tBase;
                    #pragma unroll
                    for (int ni = 0; ni < 4; ni++) {
                        int col = wn0 + ni*8 + 2*tig;
                        int t = tBase + col;
                        bool ok0 = (cbase + col < tLen) && (t >= tMin);
                        bool ok1 = (cbase + col < tLen) && (t + 1 >= tMin);
                        if (ok0 && ok1) {
                            float x0 = __bfloat162float(X2h[off+col])   + __bfloat162float(X2l[off+col]);
                            float x1 = __bfloat162float(X2h[off+col+1]) + __bfloat162float(X2l[off+col+1]);
                            float v0 = acc[mi][ni][half*2 + 0] + x0;
                            float v1 = acc[mi][ni][half*2 + 1] + x1;
                            bf16 h0, l0, h1, l1; bsplit(v0, h0, l0); bsplit(v1, h1, l1);
                            *reinterpret_cast<uint32_t*>(&O0b[off + col]) = bpack(h0, h1);
                            *reinterpret_cast<uint32_t*>(&O1b[off + col]) = bpack(l0, l1);
                        } else {
                            #pragma unroll
                            for (int e = 0; e < 2; e++) {
                                bool ok = (cbase + col + e < tLen) && (tBase + col + e >= tMin);
                                if (ok) {
                                    float xo = __bfloat162float(X2h[off+col+e])
                                             + __bfloat162float(X2l[off+col+e]);
                                    float v = acc[mi][ni][half*2 + e] + xo;
                                    bf16 vh, vl; bsplit(v, vh, vl);
                                    O0b[off + col + e] = vh;
                                    O1b[off + col + e] = vl;
                                }
                            }
                        }
                    }
                }
            }
        }
    } else {  // MODE 0 (split bf16 out) / MODE 3 (fp32 relu out)
        #pragma unroll
        for (int mi = 0; mi < 4; mi++) {
            #pragma unroll
            for (int half = 0; half < 2; half++) {
                int m = m0 + wm0 + mi*16 + g + half*8;
                float bv = bias[m];
                size_t off;
                if (MODE == 0) off = ((size_t)(bb*384 + m))*TP + tBase;
                else           off = ((size_t)(bb*512 + m))*OUTTP + tBase;
                #pragma unroll
                for (int ni = 0; ni < 4; ni++) {
                    int col = wn0 + ni*8 + 2*tig;
                    if (cbase + col < tLen) {   // even tLen => pair valid
                        float v0 = acc[mi][ni][half*2 + 0] + bv;
                        float v1 = acc[mi][ni][half*2 + 1] + bv;
                        if (MODE == 3) {
                            O0f[off + col]     = fmaxf(v0, 0.f);
                            O0f[off + col + 1] = fmaxf(v1, 0.f);
                        } else {
                            bf16 h0, l0, h1, l1; bsplit(v0, h0, l0); bsplit(v1, h1, l1);
                            *reinterpret_cast<uint32_t*>(&O0b[off + col]) = bpack(h0, h1);
                            *reinterpret_cast<uint32_t*>(&O1b[off + col]) = bpack(l0, l1);
                        }
                    }
                }
            }
        }
    }
}

// ---------------- post2 + log_softmax ----------------------------------------
__global__ __launch_bounds__(256) void post2_softmax(const float* __restrict__ H,
                                                     const float* __restrict__ W2,
                                                     const float* __restrict__ B2,
                                                     float* __restrict__ out)
{
    int b = blockIdx.y;
    int t0 = blockIdx.x * 16;
    int q = threadIdx.x;
    __shared__ float Hs[512*16];
    __shared__ float Ws[256*16];

    for (int idx = q; idx < 512*16; idx += 256) {
        int p = idx >> 4, j = idx & 15;
        int t = t0 + j;
        Hs[idx] = (t < OUTT) ? H[((size_t)(b*512 + p))*OUTTP + t] : 0.f;
    }
    float acc[16];
    float bq = B2[q];
    #pragma unroll
    for (int j = 0; j < 16; j++) acc[j] = bq;

    for (int p0 = 0; p0 < 512; p0 += 16) {
        __syncthreads();
        for (int idx = q; idx < 256*16; idx += 256) {
            int qq = idx >> 4, pp = idx & 15;
            Ws[idx] = W2[(size_t)qq*512 + p0 + pp];
        }
        __syncthreads();
        #pragma unroll
        for (int pp = 0; pp < 16; pp++) {
            float w = Ws[q*16 + pp];
            const float* hp = &Hs[(p0 + pp)*16];
            #pragma unroll
            for (int j = 0; j < 16; j++) acc[j] += w * hp[j];
        }
    }
    __syncthreads();
    #pragma unroll
    for (int j = 0; j < 16; j++) Hs[q*16 + j] = acc[j];
    __syncthreads();
    if (q < 16) {
        float mx = -1e30f;
        for (int qq = 0; qq < 256; qq++) mx = fmaxf(mx, Hs[qq*16 + q]);
        float s = 0.f;
        for (int qq = 0; qq < 256; qq++) s += expf(Hs[qq*16 + q] - mx);
        Ws[q] = mx + logf(s);
    }
    __syncthreads();
    #pragma unroll
    for (int j = 0; j < 16; j++) {
        int t = t0 + j;
        if (t < OUTT) out[((size_t)(b*256 + q))*OUTT + t] = acc[j] - Ws[j];
    }
}

// ---------------- host --------------------------------------------------------
static const int h_dils[20] = {1,2,4,8,16,32,64,128,256,512,1,2,4,8,16,32,64,128,256,512};
#define GEMM_SMEM 98304   // 3 stages x (16KB A + 16KB B)

extern "C" void kernel_launch(void* const* d_in, const int* in_sizes, int n_in,
                              void* d_out, int out_size)
{
    (void)in_sizes; (void)n_in; (void)out_size;
    const float* wav       = (const float*)d_in[0];
    const float* lc_sparse = (const float*)d_in[1];
    const float* lc_conv_w = (const float*)d_in[2];
    const float* lc_conv_b = (const float*)d_in[3];
    const float* ups_w0    = (const float*)d_in[4];
    const float* ups_b0    = (const float*)d_in[5];
    const float* ups_w1    = (const float*)d_in[6];
    const float* ups_b1    = (const float*)d_in[7];
    const float* ups_w2    = (const float*)d_in[8];
    const float* ups_b2    = (const float*)d_in[9];
    const float* ups_w3    = (const float*)d_in[10];
    const float* ups_b3    = (const float*)d_in[11];
    const float* emb_w     = (const float*)d_in[12];
    const float* emb_b     = (const float*)d_in[13];
    const float* base_w    = (const float*)d_in[14];
    const float* base_b    = (const float*)d_in[15];
    const float* sig_w     = (const float*)d_in[16];
    const float* sig_b     = (const float*)d_in[17];
    const float* gate_w    = (const float*)d_in[18];
    const float* gate_b    = (const float*)d_in[19];
    const float* psig_w    = (const float*)d_in[20];
    const float* pgate_w   = (const float*)d_in[21];
    const float* skp_w     = (const float*)d_in[22];
    const float* res_w     = (const float*)d_in[23];
    const float* post1_w   = (const float*)d_in[24];
    const float* post1_b   = (const float*)d_in[25];
    const float* post2_w   = (const float*)d_in[26];
    const float* post2_b   = (const float*)d_in[27];
    const int*   spk       = (const int*)d_in[28];
    const int*   jit       = (const int*)d_in[29];
    float* out = (float*)d_out;

    bf16 *pXh0r,*pXl0r,*pXh1r,*pXl1r,*pXshr,*pXslr,*pCh,*pCl,*pZh,*pZl,*pWh,*pWl,*pSkh,*pSkl;
    bf16 *pWcat,*pWB,*pWbA,*pWp1;
    float *pCF,*pSkip,*pH,*pfb,*pLc1,*pUpA,*pUpB;
    cudaGetSymbolAddress((void**)&pXh0r, g_Xh0);
    cudaGetSymbolAddress((void**)&pXl0r, g_Xl0);
    cudaGetSymbolAddress((void**)&pXh1r, g_Xh1);
    cudaGetSymbolAddress((void**)&pXl1r, g_Xl1);
    cudaGetSymbolAddress((void**)&pXshr, g_Xsh);
    cudaGetSymbolAddress((void**)&pXslr, g_Xsl);
    cudaGetSymbolAddress((void**)&pCh,   g_condh);
    cudaGetSymbolAddress((void**)&pCl,   g_condl);
    cudaGetSymbolAddress((void**)&pCF,   g_condF);
    cudaGetSymbolAddress((void**)&pZh,   g_Zh);
    cudaGetSymbolAddress((void**)&pZl,   g_Zl);
    cudaGetSymbolAddress((void**)&pWh,   g_wavh);
    cudaGetSymbolAddress((void**)&pWl,   g_wavl);
    cudaGetSymbolAddress((void**)&pSkip, g_skip);
    cudaGetSymbolAddress((void**)&pSkh,  g_skh);
    cudaGetSymbolAddress((void**)&pSkl,  g_skl);
    cudaGetSymbolAddress((void**)&pH,    g_H);
    cudaGetSymbolAddress((void**)&pWcat, g_Wcat);
    cudaGetSymbolAddress((void**)&pWB,   g_WB);
    cudaGetSymbolAddress((void**)&pWbA,  g_WbA);
    cudaGetSymbolAddress((void**)&pWp1,  g_Wp1);
    cudaGetSymbolAddress((void**)&pfb,   g_fb);
    cudaGetSymbolAddress((void**)&pLc1,  g_lc1);
    cudaGetSymbolAddress((void**)&pUpA,  g_upA);
    cudaGetSymbolAddress((void**)&pUpB,  g_upB);
    bf16* pXh0 = pXh0r + LEAD;  bf16* pXl0 = pXl0r + LEAD;
    bf16* pXh1 = pXh1r + LEAD;  bf16* pXl1 = pXl1r + LEAD;
    bf16* pXsh = pXshr + LEAD;  bf16* pXsl = pXslr + LEAD;

    cudaFuncSetAttribute(gemm_tc<0>, cudaFuncAttributeMaxDynamicSharedMemorySize, GEMM_SMEM);
    cudaFuncSetAttribute(gemm_tc<1>, cudaFuncAttributeMaxDynamicSharedMemorySize, GEMM_SMEM);
    cudaFuncSetAttribute(gemm_tc<2>, cudaFuncAttributeMaxDynamicSharedMemorySize, GEMM_SMEM);
    cudaFuncSetAttribute(gemm_tc<3>, cudaFuncAttributeMaxDynamicSharedMemorySize, GEMM_SMEM);

    // launch order arranged so launch index 5 (ncu -s 5 -c 1) is gemm_tc<0>
    {
        int n = 20*512*3072;                                           // launch 0
        pack_weights<<<(n + 255)/256, 256>>>(sig_w, sig_b, gate_w, gate_b,
                                             psig_w, pgate_w, skp_w, res_w,
                                             base_w, post1_w);
    }
    {
        int n = 4*256*TFULL;                                           // launch 1
        split_plane<<<(n + 255)/256, 256>>>(wav, pWh, pWl, 4*256, TFULL, TP, 0);
    }
    lc1_kernel<<<dim3(128, 4), 64>>>(lc_sparse, jit, lc_conv_w, lc_conv_b);   // 2
    tconv_kernel<<<dim3((290+127)/128, 128, 4), 128>>>(pLc1, ups_w0, ups_b0, pUpA,
        62, 290, 25, 5, 62, 128*62, 290, 128*290);                            // 3
    tconv_kernel<<<dim3((1148+127)/128, 128, 4), 128>>>(pUpA, ups_w1, ups_b1, pUpB,
        290, 1148, 16, 4, 290, 128*290, 1148, 128*1148);                      // 4
    // base 1x1 conv -> X0 planes  (launch 5 — ncu capture target)
    gemm_tc<0><<<dim3(3, (TFULL+127)/128, 4), 256, GEMM_SMEM>>>(pWbA, pWh, pWl,
        nullptr, nullptr, nullptr, nullptr, base_b,
        pXh0, pXl0, nullptr, nullptr, nullptr, nullptr, 0, TFULL, 0, 0);
    tconv_kernel<<<dim3((4580+127)/128, 128, 4), 128>>>(pUpB, ups_w2, ups_b2, pUpA,
        1148, 4580, 16, 4, 1148, 128*1148, 4580, 128*4580);                   // 6
    tconv_kernel<<<dim3((TFULL+127)/128, 128, 4), 128>>>(pUpA, ups_w3, ups_b3, pCF,
        4580, TFULL, 16, 4, 4580, 128*4580, TFULL, 128*TFULL);                // 7
    {
        int n = 4*128*TFULL;
        split_cond<<<(n + 255)/256, 256>>>(pCF, pCh, pCl);
    }
    gc_kernel<<<dim3((TFULL+255)/256, 128, 4), 256>>>(emb_w, emb_b, spk, pCh, pCl);

    // 20 residual layers
    int cum = 0;
    for (int i = 0; i < 20; i++) {
        int dil = h_dils[i];
        int cl = cum + dil;
        int tA = cl & ~7;
        int tLen = TFULL - tA;
        bf16* Xih = (i % 2 == 0) ? pXh0 : pXh1;  bf16* Xil = (i % 2 == 0) ? pXl0 : pXl1;
        bf16* Xoh = (i % 2 == 0) ? pXh1 : pXh0;  bf16* Xol = (i % 2 == 0) ? pXl1 : pXl0;
        const bf16 *Xdh, *Xdl;
        if (dil == 1) {
            int n = 4*384*TP;
            shift1<<<(n + 255)/256, 256>>>(Xih, Xil, pXsh, pXsl);
            Xdh = pXsh; Xdl = pXsl;
        } else {
            Xdh = Xih - dil; Xdl = Xil - dil;
        }
        int gx = (tLen + 127)/128;
        gemm_tc<1><<<dim3(4, gx, 4), 256, GEMM_SMEM>>>(pWcat + (size_t)i*512*3072,
            Xih, Xil, Xdh, Xdl, pCh, pCl, pfb + i*512,
            pZh, pZl, nullptr, nullptr, nullptr, nullptr, tA, tLen, 0, cl);
        gemm_tc<2><<<dim3(5, gx, 4), 256, GEMM_SMEM>>>(pWB + (size_t)i*640*768,
            pZh, pZl, nullptr, nullptr, nullptr, nullptr, nullptr,
            Xoh, Xol, nullptr, Xih, Xil, pSkip, tA, tLen, (i == 0) ? 1 : 0, cl);
        cum = cl;
    }

    {
        int n = 4*256*OUTTP;
        split_plane<<<(n + 255)/256, 256>>>(pSkip, pSkh, pSkl, 4*256, OUTTP, OUTTP, 1);
    }
    gemm_tc<3><<<dim3(4, (OUTT+127)/128, 4), 256, GEMM_SMEM>>>(pWp1, pSkh, pSkl,
        nullptr, nullptr, nullptr, nullptr, post1_b,
        nullptr, nullptr, pH, nullptr, nullptr, nullptr, 0, OUTT, 0, 0);
    post2_softmax<<<dim3((OUTT+15)/16, 4), 256>>>(pH, post2_w, post2_b, out);
}